// round 1
// baseline (speedup 1.0000x reference)
#include <cuda_runtime.h>
#include <cuda_bf16.h>

// ---------------- problem constants ----------------
#define BATCH 64
#define SEQ 197
#define NPATCH 196
#define DIM 768
#define NHEAD 12
#define DH 64
#define MLPD 3072
#define OUTD 1000
#define NLAYER 12

// ---------------- scratch (static device globals; no allocation) ----------------
__device__ float g_patches[(long long)BATCH * NPATCH * DIM];   // im2col
__device__ float g_out[(long long)BATCH * SEQ * DIM];          // residual stream
__device__ float g_xln[(long long)BATCH * SEQ * DIM];          // layernorm output
__device__ float g_q[(long long)BATCH * SEQ * DIM];
__device__ float g_k[(long long)BATCH * SEQ * DIM];
__device__ float g_v[(long long)BATCH * SEQ * DIM];
__device__ float g_att[(long long)BATCH * NHEAD * SEQ * SEQ];  // attention probs
__device__ float g_mlp[(long long)BATCH * SEQ * MLPD];         // MLP hidden

// ---------------- patchify: x (N,3,224,224) -> (N,196,768) with (c,hi,wi) flatten ----------------
__global__ void patchify_kernel(const float* __restrict__ x, float* __restrict__ out) {
    long long idx = (long long)blockIdx.x * 256 + threadIdx.x;
    const long long total = (long long)BATCH * NPATCH * DIM;
    if (idx >= total) return;
    int e = (int)(idx % DIM);
    long long r = idx / DIM;
    int p = (int)(r % NPATCH);
    int n = (int)(r / NPATCH);
    int c = e / 256;
    int hw = e % 256;
    int hi = hw / 16, wi = hw % 16;
    int pi = p / 14, pj = p % 14;
    out[idx] = x[(((long long)n * 3 + c) * 224 + (pi * 16 + hi)) * 224 + (pj * 16 + wi)];
}

// ---------------- cls + positional embedding ----------------
__global__ void clspos_kernel(float* __restrict__ out, const float* __restrict__ cls) {
    long long idx = (long long)blockIdx.x * 256 + threadIdx.x;
    const long long total = (long long)BATCH * SEQ * DIM;
    if (idx >= total) return;
    int d = (int)(idx % DIM);
    long long r = idx / DIM;
    int s = (int)(r % SEQ);
    float v = (s == 0) ? cls[d] : out[idx];
    float pe;
    if ((s & 1) == 0) {
        pe = sinf((float)s / powf(10000.0f, (float)d / (float)DIM));
    } else {
        pe = cosf((float)s / powf(10000.0f, (float)(d - 1) / (float)DIM));
    }
    out[idx] = v + pe;
}

// ---------------- layernorm over last dim (768), one block per row ----------------
__global__ void layernorm_kernel(const float* __restrict__ x, const float* __restrict__ g,
                                 const float* __restrict__ b, float* __restrict__ y) {
    long long row = blockIdx.x;
    const float* p = x + row * DIM;
    float* q = y + row * DIM;
    __shared__ float s1[256], s2[256];
    int t = threadIdx.x;
    float a = 0.f, a2 = 0.f;
    for (int j = t; j < DIM; j += 256) { float v = p[j]; a += v; a2 += v * v; }
    s1[t] = a; s2[t] = a2; __syncthreads();
    for (int s = 128; s > 0; s >>= 1) {
        if (t < s) { s1[t] += s1[t + s]; s2[t] += s2[t + s]; }
        __syncthreads();
    }
    float mu = s1[0] * (1.0f / DIM);
    float var = s2[0] * (1.0f / DIM) - mu * mu;
    float inv = rsqrtf(var + 1e-5f);
    for (int j = t; j < DIM; j += 256) q[j] = (p[j] - mu) * inv * g[j] + b[j];
}

// ---------------- softmax over rows of length ncols ----------------
__global__ void softmax_kernel(float* __restrict__ att, int ncols) {
    long long row = blockIdx.x;
    float* p = att + row * (long long)ncols;
    __shared__ float red[256];
    int t = threadIdx.x;
    float m = -1e30f;
    for (int j = t; j < ncols; j += 256) m = fmaxf(m, p[j]);
    red[t] = m; __syncthreads();
    for (int s = 128; s > 0; s >>= 1) { if (t < s) red[t] = fmaxf(red[t], red[t + s]); __syncthreads(); }
    m = red[0]; __syncthreads();
    float sum = 0.f;
    for (int j = t; j < ncols; j += 256) { float e = expf(p[j] - m); p[j] = e; sum += e; }
    red[t] = sum; __syncthreads();
    for (int s = 128; s > 0; s >>= 1) { if (t < s) red[t] += red[t + s]; __syncthreads(); }
    float inv = 1.0f / red[0];
    for (int j = t; j < ncols; j += 256) p[j] *= inv;
}

// ---------------- generic batched GEMM, C = alpha * A @ op(B) (+bias) (+gelu) (+residual) ----------------
// Batch index bz decomposes as i1 = bz / z2, i2 = bz % z2; each pointer gets i1*s1 + i2*s2.
// NT: C[m,n] = sum_k A[m*lda+k] * B[n*ldb+k]
// NN: C[m,n] = sum_k A[m*lda+k] * B[k*ldb+n]
// epi: 0 = none, 1 = exact GELU. If R != nullptr, add R[m*ldc+n] after epi.

#define BM 64
#define BN 64
#define BK 16

template <bool TRANS_B>
__global__ void gemm_kernel(
    const float* __restrict__ A, int lda, long long sA1, long long sA2,
    const float* __restrict__ B, int ldb, long long sB1, long long sB2,
    float* __restrict__ C, int ldc, long long sC1, long long sC2,
    const float* __restrict__ bias, long long sb1, long long sb2,
    const float* __restrict__ R, long long sR1, long long sR2,
    int M, int N, int K, float alpha, int epi, int z2)
{
    int bz = blockIdx.z;
    int i1 = bz / z2, i2 = bz % z2;
    A += i1 * sA1 + i2 * sA2;
    B += i1 * sB1 + i2 * sB2;
    C += i1 * sC1 + i2 * sC2;
    if (bias) bias += i1 * sb1 + i2 * sb2;
    if (R) R += i1 * sR1 + i2 * sR2;

    __shared__ float As[BK][BM];
    __shared__ float Bs[BK][BN];

    int bm = blockIdx.y * BM;
    int bn = blockIdx.x * BN;
    int tid = threadIdx.x;
    int tx = tid % 16, ty = tid / 16;

    float acc[4][4] = {};

    for (int k0 = 0; k0 < K; k0 += BK) {
        #pragma unroll
        for (int i = 0; i < 4; i++) {
            int idx = tid + i * 256;
            int m = idx / BK, kk = idx % BK;
            int gm = bm + m, gk = k0 + kk;
            As[kk][m] = (gm < M && gk < K) ? A[(long long)gm * lda + gk] : 0.f;
        }
        if (TRANS_B) {
            #pragma unroll
            for (int i = 0; i < 4; i++) {
                int idx = tid + i * 256;
                int n = idx / BK, kk = idx % BK;
                int gn = bn + n, gk = k0 + kk;
                Bs[kk][n] = (gn < N && gk < K) ? B[(long long)gn * ldb + gk] : 0.f;
            }
        } else {
            #pragma unroll
            for (int i = 0; i < 4; i++) {
                int idx = tid + i * 256;
                int kk = idx / BN, n = idx % BN;
                int gn = bn + n, gk = k0 + kk;
                Bs[kk][n] = (gn < N && gk < K) ? B[(long long)gk * ldb + gn] : 0.f;
            }
        }
        __syncthreads();
        #pragma unroll
        for (int kk = 0; kk < BK; kk++) {
            float a[4], b[4];
            #pragma unroll
            for (int i = 0; i < 4; i++) a[i] = As[kk][ty * 4 + i];
            #pragma unroll
            for (int j = 0; j < 4; j++) b[j] = Bs[kk][tx * 4 + j];
            #pragma unroll
            for (int i = 0; i < 4; i++)
                #pragma unroll
                for (int j = 0; j < 4; j++)
                    acc[i][j] += a[i] * b[j];
        }
        __syncthreads();
    }

    #pragma unroll
    for (int i = 0; i < 4; i++) {
        int gm = bm + ty * 4 + i;
        if (gm >= M) continue;
        #pragma unroll
        for (int j = 0; j < 4; j++) {
            int gn = bn + tx * 4 + j;
            if (gn >= N) continue;
            float v = acc[i][j] * alpha;
            if (bias) v += bias[gn];
            if (epi == 1) v = 0.5f * v * (1.0f + erff(v * 0.70710678118654752f));
            if (R) v += R[(long long)gm * ldc + gn];
            C[(long long)gm * ldc + gn] = v;
        }
    }
}

// ---------------- host-side launch helpers ----------------
struct GemmArgs {
    const float* A; int lda; long long sA1, sA2;
    const float* B; int ldb; long long sB1, sB2;
    float* C; int ldc; long long sC1, sC2;
    const float* bias; long long sb1, sb2;
    const float* R; long long sR1, sR2;
    int M, N, K; float alpha; int epi; int z2; int Z;
};

static void launch_gemm(const GemmArgs& a, bool transB, cudaStream_t stream) {
    dim3 grid((a.N + BN - 1) / BN, (a.M + BM - 1) / BM, a.Z);
    if (transB)
        gemm_kernel<true><<<grid, 256, 0, stream>>>(
            a.A, a.lda, a.sA1, a.sA2, a.B, a.ldb, a.sB1, a.sB2,
            a.C, a.ldc, a.sC1, a.sC2, a.bias, a.sb1, a.sb2,
            a.R, a.sR1, a.sR2, a.M, a.N, a.K, a.alpha, a.epi, a.z2);
    else
        gemm_kernel<false><<<grid, 256, 0, stream>>>(
            a.A, a.lda, a.sA1, a.sA2, a.B, a.ldb, a.sB1, a.sB2,
            a.C, a.ldc, a.sC1, a.sC2, a.bias, a.sb1, a.sb2,
            a.R, a.sR1, a.sR2, a.M, a.N, a.K, a.alpha, a.epi, a.z2);
}

extern "C" void kernel_launch(void* const* d_in, const int* in_sizes, int n_in,
                              void* d_out, int out_size) {
    (void)in_sizes; (void)n_in; (void)out_size;
    const float* x    = (const float*)d_in[0];
    const float* Wp   = (const float*)d_in[1];
    const float* bp   = (const float*)d_in[2];
    const float* cls  = (const float*)d_in[3];
    const float* ln1g = (const float*)d_in[4];
    const float* ln1b = (const float*)d_in[5];
    const float* Wq   = (const float*)d_in[6];
    const float* bq   = (const float*)d_in[7];
    const float* Wk   = (const float*)d_in[8];
    const float* bk   = (const float*)d_in[9];
    const float* Wv   = (const float*)d_in[10];
    const float* bv   = (const float*)d_in[11];
    const float* ln2g = (const float*)d_in[12];
    const float* ln2b = (const float*)d_in[13];
    const float* W1   = (const float*)d_in[14];
    const float* b1   = (const float*)d_in[15];
    const float* W2   = (const float*)d_in[16];
    const float* b2   = (const float*)d_in[17];
    const float* Wh   = (const float*)d_in[18];
    const float* bh   = (const float*)d_in[19];
    float* out_final  = (float*)d_out;

    float *patches, *outb, *xln, *q, *k, *v, *att, *mlp;
    cudaGetSymbolAddress((void**)&patches, g_patches);
    cudaGetSymbolAddress((void**)&outb,    g_out);
    cudaGetSymbolAddress((void**)&xln,     g_xln);
    cudaGetSymbolAddress((void**)&q,       g_q);
    cudaGetSymbolAddress((void**)&k,       g_k);
    cudaGetSymbolAddress((void**)&v,       g_v);
    cudaGetSymbolAddress((void**)&att,     g_att);
    cudaGetSymbolAddress((void**)&mlp,     g_mlp);

    cudaStream_t stream = 0;
    const long long SD = (long long)SEQ * DIM;          // 151296 per-image stride
    const long long SS = (long long)SEQ * SEQ;          // 38809

    // 1) patchify
    {
        long long total = (long long)BATCH * NPATCH * DIM;
        patchify_kernel<<<(unsigned)((total + 255) / 256), 256, 0, stream>>>(x, patches);
    }
    // 2) patch embedding GEMM: per-image batch, write rows s=1..196 of outb
    {
        GemmArgs a = {};
        a.A = patches; a.lda = DIM; a.sA1 = (long long)NPATCH * DIM; a.sA2 = 0;
        a.B = Wp; a.ldb = DIM; a.sB1 = 0; a.sB2 = 0;
        a.C = outb + DIM; a.ldc = DIM; a.sC1 = SD; a.sC2 = 0;
        a.bias = bp; a.sb1 = 0; a.sb2 = 0;
        a.R = nullptr; a.sR1 = 0; a.sR2 = 0;
        a.M = NPATCH; a.N = DIM; a.K = DIM; a.alpha = 1.0f; a.epi = 0; a.z2 = 1; a.Z = BATCH;
        launch_gemm(a, true, stream);
    }
    // 3) cls + positional embedding
    {
        long long total = (long long)BATCH * SEQ * DIM;
        clspos_kernel<<<(unsigned)((total + 255) / 256), 256, 0, stream>>>(outb, cls);
    }

    const int ROWS = BATCH * SEQ; // 12608

    for (int l = 0; l < NLAYER; l++) {
        // --- ln1 ---
        layernorm_kernel<<<ROWS, 256, 0, stream>>>(outb, ln1g + l * DIM, ln1b + l * DIM, xln);

        // --- q/k/v per-head projections: batch over heads (Z=12) ---
        const float* Ws[3] = { Wq, Wk, Wv };
        const float* bs[3] = { bq, bk, bv };
        float* Cs[3] = { q, k, v };
        for (int t = 0; t < 3; t++) {
            GemmArgs a = {};
            a.A = xln; a.lda = DIM; a.sA1 = DH; a.sA2 = 0;
            a.B = Ws[t] + (long long)l * NHEAD * DH * DH; a.ldb = DH; a.sB1 = (long long)DH * DH; a.sB2 = 0;
            a.C = Cs[t]; a.ldc = DIM; a.sC1 = DH; a.sC2 = 0;
            a.bias = bs[t] + (long long)l * NHEAD * DH; a.sb1 = DH; a.sb2 = 0;
            a.R = nullptr;
            a.M = ROWS; a.N = DH; a.K = DH; a.alpha = 1.0f; a.epi = 0; a.z2 = 1; a.Z = NHEAD;
            launch_gemm(a, true, stream);
        }

        // --- attention scores: att[n,h] = q[n,:,h,:] @ k[n,:,h,:]^T / 8 ---
        {
            GemmArgs a = {};
            a.A = q; a.lda = DIM; a.sA1 = SD; a.sA2 = DH;
            a.B = k; a.ldb = DIM; a.sB1 = SD; a.sB2 = DH;
            a.C = att; a.ldc = SEQ; a.sC1 = (long long)NHEAD * SS; a.sC2 = SS;
            a.bias = nullptr; a.R = nullptr;
            a.M = SEQ; a.N = SEQ; a.K = DH; a.alpha = 0.125f; a.epi = 0;
            a.z2 = NHEAD; a.Z = BATCH * NHEAD;
            launch_gemm(a, true, stream);
        }
        // --- softmax ---
        softmax_kernel<<<BATCH * NHEAD * SEQ, 256, 0, stream>>>(att, SEQ);

        // --- AV + residual: out += att @ v ---
        {
            GemmArgs a = {};
            a.A = att; a.lda = SEQ; a.sA1 = (long long)NHEAD * SS; a.sA2 = SS;
            a.B = v; a.ldb = DIM; a.sB1 = SD; a.sB2 = DH;
            a.C = outb; a.ldc = DIM; a.sC1 = SD; a.sC2 = DH;
            a.bias = nullptr;
            a.R = outb; a.sR1 = SD; a.sR2 = DH;
            a.M = SEQ; a.N = DH; a.K = SEQ; a.alpha = 1.0f; a.epi = 0;
            a.z2 = NHEAD; a.Z = BATCH * NHEAD;
            launch_gemm(a, false, stream);
        }

        // --- ln2 ---
        layernorm_kernel<<<ROWS, 256, 0, stream>>>(outb, ln2g + l * DIM, ln2b + l * DIM, xln);

        // --- MLP1 + GELU ---
        {
            GemmArgs a = {};
            a.A = xln; a.lda = DIM; a.sA1 = 0; a.sA2 = 0;
            a.B = W1 + (long long)l * MLPD * DIM; a.ldb = DIM; a.sB1 = 0; a.sB2 = 0;
            a.C = mlp; a.ldc = MLPD; a.sC1 = 0; a.sC2 = 0;
            a.bias = b1 + (long long)l * MLPD; a.sb1 = 0; a.sb2 = 0;
            a.R = nullptr;
            a.M = ROWS; a.N = MLPD; a.K = DIM; a.alpha = 1.0f; a.epi = 1; a.z2 = 1; a.Z = 1;
            launch_gemm(a, true, stream);
        }
        // --- MLP2 + residual ---
        {
            GemmArgs a = {};
            a.A = mlp; a.lda = MLPD; a.sA1 = 0; a.sA2 = 0;
            a.B = W2 + (long long)l * DIM * MLPD; a.ldb = MLPD; a.sB1 = 0; a.sB2 = 0;
            a.C = outb; a.ldc = DIM; a.sC1 = 0; a.sC2 = 0;
            a.bias = b2 + (long long)l * DIM; a.sb1 = 0; a.sb2 = 0;
            a.R = outb; a.sR1 = 0; a.sR2 = 0;
            a.M = ROWS; a.N = DIM; a.K = MLPD; a.alpha = 1.0f; a.epi = 0; a.z2 = 1; a.Z = 1;
            launch_gemm(a, true, stream);
        }
    }

    // --- head: out_final = out[:,0,:] @ Wh^T + bh ---
    {
        GemmArgs a = {};
        a.A = outb; a.lda = (int)SD; a.sA1 = 0; a.sA2 = 0;   // row n at n*SEQ*DIM (cls token)
        a.B = Wh; a.ldb = DIM; a.sB1 = 0; a.sB2 = 0;
        a.C = out_final; a.ldc = OUTD; a.sC1 = 0; a.sC2 = 0;
        a.bias = bh; a.sb1 = 0; a.sb2 = 0;
        a.R = nullptr;
        a.M = BATCH; a.N = OUTD; a.K = DIM; a.alpha = 1.0f; a.epi = 0; a.z2 = 1; a.Z = 1;
        launch_gemm(a, true, stream);
    }
}

// round 3
// speedup vs baseline: 3.0694x; 3.0694x over previous
#include <cuda_runtime.h>
#include <cuda_bf16.h>
#include <cstdint>

// ---------------- problem constants ----------------
#define BATCH 64
#define SEQ 197
#define NPATCH 196
#define DIM 768
#define NHEAD 12
#define DH 64
#define MLPD 3072
#define OUTD 1000
#define NLAYER 12

// ---------------- scratch (static device globals; no allocation) ----------------
__device__ float g_out[(long long)BATCH * SEQ * DIM];          // residual stream
__device__ float g_xln[(long long)BATCH * SEQ * DIM];          // layernorm output (fp32)
__device__ float g_q[(long long)BATCH * SEQ * DIM];
__device__ float g_k[(long long)BATCH * SEQ * DIM];
__device__ float g_v[(long long)BATCH * SEQ * DIM];
__device__ float g_att[(long long)BATCH * NHEAD * SEQ * SEQ];  // attention probs
__device__ float g_ptmp[(long long)BATCH * NPATCH * DIM];      // patch-embed fp32 out

// bf16 hi/lo planes
__device__ __nv_bfloat16 g_ph[(long long)BATCH * NPATCH * DIM];   // patches
__device__ __nv_bfloat16 g_pl[(long long)BATCH * NPATCH * DIM];
__device__ __nv_bfloat16 g_xh[(long long)BATCH * SEQ * DIM];      // ln2 out
__device__ __nv_bfloat16 g_xl[(long long)BATCH * SEQ * DIM];
__device__ __nv_bfloat16 g_mh[(long long)BATCH * SEQ * MLPD];     // mlp hidden
__device__ __nv_bfloat16 g_ml[(long long)BATCH * SEQ * MLPD];
__device__ __nv_bfloat16 g_wph[(long long)DIM * DIM];             // Wp
__device__ __nv_bfloat16 g_wpl[(long long)DIM * DIM];
__device__ __nv_bfloat16 g_w1h[(long long)NLAYER * MLPD * DIM];   // W1
__device__ __nv_bfloat16 g_w1l[(long long)NLAYER * MLPD * DIM];
__device__ __nv_bfloat16 g_w2h[(long long)NLAYER * DIM * MLPD];   // W2
__device__ __nv_bfloat16 g_w2l[(long long)NLAYER * DIM * MLPD];

// ---------------- helpers ----------------
__device__ __forceinline__ uint32_t smem_u32(const void* p) {
    uint32_t a;
    asm("{ .reg .u64 t; cvta.to.shared.u64 t, %1; cvt.u32.u64 %0, t; }" : "=r"(a) : "l"(p));
    return a;
}

__device__ __forceinline__ void bf16_split(float x, __nv_bfloat16& h, __nv_bfloat16& l) {
    h = __float2bfloat16_rn(x);
    l = __float2bfloat16_rn(x - __bfloat162float(h));
}

__device__ __forceinline__ void ldm4(uint32_t* r, uint32_t addr) {
    asm volatile("ldmatrix.sync.aligned.m8n8.x4.shared.b16 {%0,%1,%2,%3}, [%4];"
                 : "=r"(r[0]), "=r"(r[1]), "=r"(r[2]), "=r"(r[3]) : "r"(addr));
}

__device__ __forceinline__ void mma_bf16(float* c, const uint32_t* a, uint32_t b0, uint32_t b1) {
    asm volatile(
        "mma.sync.aligned.m16n8k16.row.col.f32.bf16.bf16.f32 "
        "{%0,%1,%2,%3}, {%4,%5,%6,%7}, {%8,%9}, {%0,%1,%2,%3};"
        : "+f"(c[0]), "+f"(c[1]), "+f"(c[2]), "+f"(c[3])
        : "r"(a[0]), "r"(a[1]), "r"(a[2]), "r"(a[3]), "r"(b0), "r"(b1));
}

__device__ __forceinline__ void cp_async16(uint32_t dst, const void* src, int valid) {
    asm volatile("cp.async.cg.shared.global [%0], [%1], 16, %2;"
                 :: "r"(dst), "l"(src), "r"(valid));
}
__device__ __forceinline__ void cp_commit() { asm volatile("cp.async.commit_group;"); }
__device__ __forceinline__ void cp_wait1() { asm volatile("cp.async.wait_group 1;"); }
__device__ __forceinline__ void cp_wait0() { asm volatile("cp.async.wait_group 0;"); }

// ======================================================================
//  bf16x3 NT GEMM:  C[M,N] = A[M,K] @ B[N,K]^T (+bias) (+gelu) (+R)
//  A,B given as bf16 hi/lo planes. 128x128x32 tiles, 8 warps (64x32 each),
//  3-stage cp.async pipeline. Output: fp32 C, or bf16 hi/lo planes.
// ======================================================================
#define RSB 80                 // smem row stride bytes (32 bf16 data + pad)
#define PLB (128 * RSB)        // plane bytes = 10240
#define STB (4 * PLB)          // stage bytes (Ahi,Alo,Bhi,Blo) = 40960
#define NSTAGE 3
#define SMEM_MMA (NSTAGE * STB)

__global__ __launch_bounds__(256, 1)
void gemm_bf16x3_kernel(const __nv_bfloat16* __restrict__ Ah, const __nv_bfloat16* __restrict__ Al,
                        long long lda,
                        const __nv_bfloat16* __restrict__ Bh, const __nv_bfloat16* __restrict__ Bl,
                        long long ldb,
                        float* __restrict__ Cf,
                        __nv_bfloat16* __restrict__ Chi, __nv_bfloat16* __restrict__ Clo,
                        long long ldc,
                        const float* __restrict__ bias, const float* __restrict__ R,
                        int M, int N, int K, int gelu)
{
    extern __shared__ char sm[];
    uint32_t smb = smem_u32(sm);
    const int tid = threadIdx.x;
    const int wid = tid >> 5, lid = tid & 31;
    const int wm = wid >> 2;          // 0..1  (64-row slab)
    const int wn = wid & 3;           // 0..3  (32-col slab)
    const int m0 = blockIdx.y * 128;
    const int n0 = blockIdx.x * 128;

    const int nch = K >> 5;           // K / 32

    // ---- async loader: one 32-wide K chunk into stage s ----
    auto load_stage = [&](int s, int chunk) {
        int k0 = chunk << 5;
        uint32_t sbase = smb + s * STB;
        #pragma unroll
        for (int t = 0; t < 8; t++) {
            int id = tid + t * 256;          // 0..2047
            int plane = id >> 9;             // 0..3
            int rc = id & 511;
            int row = rc >> 2;               // 0..127
            int c = rc & 3;                  // 16B chunk within 64B row
            uint32_t dst = sbase + plane * PLB + row * RSB + c * 16;
            const __nv_bfloat16* src;
            int valid;
            if (plane < 2) {
                int gm = m0 + row;
                int gmc = gm < M ? gm : M - 1;
                src = (plane == 0 ? Ah : Al) + (long long)gmc * lda + k0 + c * 8;
                valid = (gm < M) ? 16 : 0;
            } else {
                int gn = n0 + row;
                int gnc = gn < N ? gn : N - 1;
                src = (plane == 2 ? Bh : Bl) + (long long)gnc * ldb + k0 + c * 8;
                valid = (gn < N) ? 16 : 0;
            }
            cp_async16(dst, src, valid);
        }
        cp_commit();
    };

    float acc[4][4][4];
    #pragma unroll
    for (int i = 0; i < 4; i++)
        #pragma unroll
        for (int j = 0; j < 4; j++)
            #pragma unroll
            for (int r = 0; r < 4; r++) acc[i][j][r] = 0.f;

    // prologue
    load_stage(0, 0);
    if (nch > 1) load_stage(1, 1);

    for (int i = 0; i < nch; i++) {
        if (i == nch - 1) cp_wait0(); else cp_wait1();
        __syncthreads();
        if (i + 2 < nch) load_stage((i + 2) % NSTAGE, i + 2);

        uint32_t sA = smb + (i % NSTAGE) * STB;
        uint32_t sB = sA + 2 * PLB;
        #pragma unroll
        for (int kk = 0; kk < 2; kk++) {
            int kt = kk << 4;
            uint32_t ah[4][4], al[4][4];
            #pragma unroll
            for (int t = 0; t < 4; t++) {
                int m = wm * 64 + t * 16;
                uint32_t row = m + ((lid >> 3) & 1) * 8 + (lid & 7);
                uint32_t koff = kt + (lid >> 4) * 8;
                uint32_t ad = sA + row * RSB + koff * 2;
                ldm4(ah[t], ad);
                ldm4(al[t], ad + PLB);
            }
            uint32_t bh[2][4], bl[2][4];
            #pragma unroll
            for (int p = 0; p < 2; p++) {
                int n = wn * 32 + p * 16;
                uint32_t row = n + (lid >> 4) * 8 + (lid & 7);
                uint32_t koff = kt + ((lid >> 3) & 1) * 8;
                uint32_t bd = sB + row * RSB + koff * 2;
                ldm4(bh[p], bd);
                ldm4(bl[p], bd + PLB);
            }
            #pragma unroll
            for (int t = 0; t < 4; t++) {
                #pragma unroll
                for (int j = 0; j < 4; j++) {
                    uint32_t b0h = bh[j >> 1][(j & 1) * 2], b1h = bh[j >> 1][(j & 1) * 2 + 1];
                    uint32_t b0l = bl[j >> 1][(j & 1) * 2], b1l = bl[j >> 1][(j & 1) * 2 + 1];
                    mma_bf16(acc[t][j], ah[t], b0h, b1h);
                    mma_bf16(acc[t][j], al[t], b0h, b1h);
                    mma_bf16(acc[t][j], ah[t], b0l, b1l);
                }
            }
        }
        __syncthreads();
    }

    // ---- epilogue ----
    #pragma unroll
    for (int t = 0; t < 4; t++) {
        #pragma unroll
        for (int j = 0; j < 4; j++) {
            int col = n0 + wn * 32 + j * 8 + (lid & 3) * 2;
            #pragma unroll
            for (int h = 0; h < 2; h++) {
                int row = m0 + wm * 64 + t * 16 + (lid >> 2) + h * 8;
                if (row >= M) continue;
                long long base = (long long)row * ldc + col;
                #pragma unroll
                for (int e = 0; e < 2; e++) {
                    float v = acc[t][j][h * 2 + e];
                    int c = col + e;
                    if (bias) v += bias[c];
                    if (gelu) v = 0.5f * v * (1.0f + erff(v * 0.70710678118654752f));
                    if (Cf) {
                        float r = R ? R[base + e] : 0.f;
                        Cf[base + e] = v + r;
                    } else {
                        __nv_bfloat16 hh, ll;
                        bf16_split(v, hh, ll);
                        Chi[base + e] = hh;
                        Clo[base + e] = ll;
                    }
                }
            }
        }
    }
}

// ======================================================================
//  small kernels
// ======================================================================
__global__ void split_kernel(const float* __restrict__ x, __nv_bfloat16* __restrict__ h,
                             __nv_bfloat16* __restrict__ l, long long n) {
    long long i = ((long long)blockIdx.x * 256 + threadIdx.x) * 4;
    if (i >= n) return;
    float4 v = *(const float4*)(x + i);
    __nv_bfloat16 hh, ll;
    bf16_split(v.x, hh, ll); h[i] = hh; l[i] = ll;
    bf16_split(v.y, hh, ll); h[i + 1] = hh; l[i + 1] = ll;
    bf16_split(v.z, hh, ll); h[i + 2] = hh; l[i + 2] = ll;
    bf16_split(v.w, hh, ll); h[i + 3] = hh; l[i + 3] = ll;
}

__global__ void patchify_kernel(const float* __restrict__ x,
                                __nv_bfloat16* __restrict__ ph, __nv_bfloat16* __restrict__ pl) {
    long long idx = (long long)blockIdx.x * 256 + threadIdx.x;
    const long long total = (long long)BATCH * NPATCH * DIM;
    if (idx >= total) return;
    int e = (int)(idx % DIM);
    long long r = idx / DIM;
    int p = (int)(r % NPATCH);
    int n = (int)(r / NPATCH);
    int c = e / 256;
    int hw = e % 256;
    int hi = hw / 16, wi = hw % 16;
    int pi = p / 14, pj = p % 14;
    float v = x[(((long long)n * 3 + c) * 224 + (pi * 16 + hi)) * 224 + (pj * 16 + wi)];
    __nv_bfloat16 hh, ll;
    bf16_split(v, hh, ll);
    ph[idx] = hh; pl[idx] = ll;
}

__global__ void assemble_kernel(const float* __restrict__ tmp, const float* __restrict__ cls,
                                float* __restrict__ out) {
    long long idx = (long long)blockIdx.x * 256 + threadIdx.x;
    const long long total = (long long)BATCH * SEQ * DIM;
    if (idx >= total) return;
    int d = (int)(idx % DIM);
    long long r = idx / DIM;
    int s = (int)(r % SEQ);
    int n = (int)(r / SEQ);
    float v = (s == 0) ? cls[d] : tmp[((long long)n * NPATCH + (s - 1)) * DIM + d];
    float pe;
    if ((s & 1) == 0) pe = sinf((float)s / powf(10000.0f, (float)d / (float)DIM));
    else              pe = cosf((float)s / powf(10000.0f, (float)(d - 1) / (float)DIM));
    out[idx] = v + pe;
}

// layernorm; optionally emit bf16 hi/lo planes
__global__ void layernorm_kernel(const float* __restrict__ x, const float* __restrict__ g,
                                 const float* __restrict__ b, float* __restrict__ y,
                                 __nv_bfloat16* __restrict__ yh, __nv_bfloat16* __restrict__ yl) {
    long long row = blockIdx.x;
    const float* p = x + row * DIM;
    __shared__ float s1[256], s2[256];
    int t = threadIdx.x;
    float a = 0.f, a2 = 0.f;
    for (int j = t; j < DIM; j += 256) { float v = p[j]; a += v; a2 += v * v; }
    s1[t] = a; s2[t] = a2; __syncthreads();
    for (int s = 128; s > 0; s >>= 1) {
        if (t < s) { s1[t] += s1[t + s]; s2[t] += s2[t + s]; }
        __syncthreads();
    }
    float mu = s1[0] * (1.0f / DIM);
    float var = s2[0] * (1.0f / DIM) - mu * mu;
    float inv = rsqrtf(var + 1e-5f);
    for (int j = t; j < DIM; j += 256) {
        float v = (p[j] - mu) * inv * g[j] + b[j];
        if (y) y[row * DIM + j] = v;
        if (yh) {
            __nv_bfloat16 hh, ll;
            bf16_split(v, hh, ll);
            yh[row * DIM + j] = hh; yl[row * DIM + j] = ll;
        }
    }
}

__global__ void softmax_kernel(float* __restrict__ att, int ncols) {
    long long row = blockIdx.x;
    float* p = att + row * (long long)ncols;
    __shared__ float red[256];
    int t = threadIdx.x;
    float m = -1e30f;
    for (int j = t; j < ncols; j += 256) m = fmaxf(m, p[j]);
    red[t] = m; __syncthreads();
    for (int s = 128; s > 0; s >>= 1) { if (t < s) red[t] = fmaxf(red[t], red[t + s]); __syncthreads(); }
    m = red[0]; __syncthreads();
    float sum = 0.f;
    for (int j = t; j < ncols; j += 256) { float e = expf(p[j] - m); p[j] = e; sum += e; }
    red[t] = sum; __syncthreads();
    for (int s = 128; s > 0; s >>= 1) { if (t < s) red[t] += red[t + s]; __syncthreads(); }
    float inv = 1.0f / red[0];
    for (int j = t; j < ncols; j += 256) p[j] *= inv;
}

// ======================================================================
//  generic SIMT batched GEMM (attention / qkv / head)
// ======================================================================
#define BM 64
#define BN 64
#define BK 16

template <bool TRANS_B>
__global__ void gemm_kernel(
    const float* __restrict__ A, int lda, long long sA1, long long sA2,
    const float* __restrict__ B, int ldb, long long sB1, long long sB2,
    float* __restrict__ C, int ldc, long long sC1, long long sC2,
    const float* __restrict__ bias, long long sb1, long long sb2,
    const float* __restrict__ R, long long sR1, long long sR2,
    int M, int N, int K, float alpha, int epi, int z2)
{
    int bz = blockIdx.z;
    int i1 = bz / z2, i2 = bz % z2;
    A += i1 * sA1 + i2 * sA2;
    B += i1 * sB1 + i2 * sB2;
    C += i1 * sC1 + i2 * sC2;
    if (bias) bias += i1 * sb1 + i2 * sb2;
    if (R) R += i1 * sR1 + i2 * sR2;

    __shared__ float As[BK][BM];
    __shared__ float Bs[BK][BN];

    int bm = blockIdx.y * BM;
    int bn = blockIdx.x * BN;
    int tid = threadIdx.x;
    int tx = tid % 16, ty = tid / 16;

    float acc[4][4] = {};

    for (int k0 = 0; k0 < K; k0 += BK) {
        #pragma unroll
        for (int i = 0; i < 4; i++) {
            int idx = tid + i * 256;
            int m = idx / BK, kk = idx % BK;
            int gm = bm + m, gk = k0 + kk;
            As[kk][m] = (gm < M && gk < K) ? A[(long long)gm * lda + gk] : 0.f;
        }
        if (TRANS_B) {
            #pragma unroll
            for (int i = 0; i < 4; i++) {
                int idx = tid + i * 256;
                int n = idx / BK, kk = idx % BK;
                int gn = bn + n, gk = k0 + kk;
                Bs[kk][n] = (gn < N && gk < K) ? B[(long long)gn * ldb + gk] : 0.f;
            }
        } else {
            #pragma unroll
            for (int i = 0; i < 4; i++) {
                int idx = tid + i * 256;
                int kk = idx / BN, n = idx % BN;
                int gn = bn + n, gk = k0 + kk;
                Bs[kk][n] = (gn < N && gk < K) ? B[(long long)gk * ldb + gn] : 0.f;
            }
        }
        __syncthreads();
        #pragma unroll
        for (int kk = 0; kk < BK; kk++) {
            float a[4], b[4];
            #pragma unroll
            for (int i = 0; i < 4; i++) a[i] = As[kk][ty * 4 + i];
            #pragma unroll
            for (int j = 0; j < 4; j++) b[j] = Bs[kk][tx * 4 + j];
            #pragma unroll
            for (int i = 0; i < 4; i++)
                #pragma unroll
                for (int j = 0; j < 4; j++)
                    acc[i][j] += a[i] * b[j];
        }
        __syncthreads();
    }

    #pragma unroll
    for (int i = 0; i < 4; i++) {
        int gm = bm + ty * 4 + i;
        if (gm >= M) continue;
        #pragma unroll
        for (int j = 0; j < 4; j++) {
            int gn = bn + tx * 4 + j;
            if (gn >= N) continue;
            float v = acc[i][j] * alpha;
            if (bias) v += bias[gn];
            if (epi == 1) v = 0.5f * v * (1.0f + erff(v * 0.70710678118654752f));
            if (R) v += R[(long long)gm * ldc + gn];
            C[(long long)gm * ldc + gn] = v;
        }
    }
}

struct GemmArgs {
    const float* A; int lda; long long sA1, sA2;
    const float* B; int ldb; long long sB1, sB2;
    float* C; int ldc; long long sC1, sC2;
    const float* bias; long long sb1, sb2;
    const float* R; long long sR1, sR2;
    int M, N, K; float alpha; int epi; int z2; int Z;
};

static void launch_gemm(const GemmArgs& a, bool transB, cudaStream_t stream) {
    dim3 grid((a.N + BN - 1) / BN, (a.M + BM - 1) / BM, a.Z);
    if (transB)
        gemm_kernel<true><<<grid, 256, 0, stream>>>(
            a.A, a.lda, a.sA1, a.sA2, a.B, a.ldb, a.sB1, a.sB2,
            a.C, a.ldc, a.sC1, a.sC2, a.bias, a.sb1, a.sb2,
            a.R, a.sR1, a.sR2, a.M, a.N, a.K, a.alpha, a.epi, a.z2);
    else
        gemm_kernel<false><<<grid, 256, 0, stream>>>(
            a.A, a.lda, a.sA1, a.sA2, a.B, a.ldb, a.sB1, a.sB2,
            a.C, a.ldc, a.sC1, a.sC2, a.bias, a.sb1, a.sb2,
            a.R, a.sR1, a.sR2, a.M, a.N, a.K, a.alpha, a.epi, a.z2);
}

static void launch_mma(const __nv_bfloat16* Ah, const __nv_bfloat16* Al, long long lda,
                       const __nv_bfloat16* Bh, const __nv_bfloat16* Bl, long long ldb,
                       float* Cf, __nv_bfloat16* Chi, __nv_bfloat16* Clo, long long ldc,
                       const float* bias, const float* R,
                       int M, int N, int K, int gelu, cudaStream_t stream) {
    static bool attr_set = false;
    if (!attr_set) {
        cudaFuncSetAttribute(gemm_bf16x3_kernel,
                             cudaFuncAttributeMaxDynamicSharedMemorySize, SMEM_MMA);
        attr_set = true;
    }
    dim3 grid(N / 128, (M + 127) / 128);
    gemm_bf16x3_kernel<<<grid, 256, SMEM_MMA, stream>>>(
        Ah, Al, lda, Bh, Bl, ldb, Cf, Chi, Clo, ldc, bias, R, M, N, K, gelu);
}

// ======================================================================
//  orchestration
// ======================================================================
extern "C" void kernel_launch(void* const* d_in, const int* in_sizes, int n_in,
                              void* d_out, int out_size) {
    (void)in_sizes; (void)n_in; (void)out_size;
    const float* x    = (const float*)d_in[0];
    const float* Wp   = (const float*)d_in[1];
    const float* bp   = (const float*)d_in[2];
    const float* cls  = (const float*)d_in[3];
    const float* ln1g = (const float*)d_in[4];
    const float* ln1b = (const float*)d_in[5];
    const float* Wq   = (const float*)d_in[6];
    const float* bq   = (const float*)d_in[7];
    const float* Wk   = (const float*)d_in[8];
    const float* bk   = (const float*)d_in[9];
    const float* Wv   = (const float*)d_in[10];
    const float* bv   = (const float*)d_in[11];
    const float* ln2g = (const float*)d_in[12];
    const float* ln2b = (const float*)d_in[13];
    const float* W1   = (const float*)d_in[14];
    const float* b1   = (const float*)d_in[15];
    const float* W2   = (const float*)d_in[16];
    const float* b2   = (const float*)d_in[17];
    const float* Wh   = (const float*)d_in[18];
    const float* bh   = (const float*)d_in[19];
    float* out_final  = (float*)d_out;

    float *outb, *xln, *q, *k, *v, *att, *ptmp;
    __nv_bfloat16 *ph, *pl, *xh, *xl, *mh, *ml, *wph, *wpl, *w1h, *w1l, *w2h, *w2l;
    cudaGetSymbolAddress((void**)&outb, g_out);
    cudaGetSymbolAddress((void**)&xln,  g_xln);
    cudaGetSymbolAddress((void**)&q,    g_q);
    cudaGetSymbolAddress((void**)&k,    g_k);
    cudaGetSymbolAddress((void**)&v,    g_v);
    cudaGetSymbolAddress((void**)&att,  g_att);
    cudaGetSymbolAddress((void**)&ptmp, g_ptmp);
    cudaGetSymbolAddress((void**)&ph,   g_ph);
    cudaGetSymbolAddress((void**)&pl,   g_pl);
    cudaGetSymbolAddress((void**)&xh,   g_xh);
    cudaGetSymbolAddress((void**)&xl,   g_xl);
    cudaGetSymbolAddress((void**)&mh,   g_mh);
    cudaGetSymbolAddress((void**)&ml,   g_ml);
    cudaGetSymbolAddress((void**)&wph,  g_wph);
    cudaGetSymbolAddress((void**)&wpl,  g_wpl);
    cudaGetSymbolAddress((void**)&w1h,  g_w1h);
    cudaGetSymbolAddress((void**)&w1l,  g_w1l);
    cudaGetSymbolAddress((void**)&w2h,  g_w2h);
    cudaGetSymbolAddress((void**)&w2l,  g_w2l);

    cudaStream_t stream = 0;
    const long long SD = (long long)SEQ * DIM;
    const long long SS = (long long)SEQ * SEQ;

    // 0) weight splits (once per launch)
    {
        long long n;
        n = (long long)DIM * DIM;
        split_kernel<<<(unsigned)((n / 4 + 255) / 256), 256, 0, stream>>>(Wp, wph, wpl, n);
        n = (long long)NLAYER * MLPD * DIM;
        split_kernel<<<(unsigned)((n / 4 + 255) / 256), 256, 0, stream>>>(W1, w1h, w1l, n);
        split_kernel<<<(unsigned)((n / 4 + 255) / 256), 256, 0, stream>>>(W2, w2h, w2l, n);
    }

    // 1) patchify -> bf16 planes
    {
        long long total = (long long)BATCH * NPATCH * DIM;
        patchify_kernel<<<(unsigned)((total + 255) / 256), 256, 0, stream>>>(x, ph, pl);
    }
    // 2) patch embedding (mma): ptmp = patches @ Wp^T + bp
    launch_mma(ph, pl, DIM, wph, wpl, DIM, ptmp, nullptr, nullptr, DIM,
               bp, nullptr, BATCH * NPATCH, DIM, DIM, 0, stream);
    // 3) assemble tokens + cls + positional embedding
    {
        long long total = (long long)BATCH * SEQ * DIM;
        assemble_kernel<<<(unsigned)((total + 255) / 256), 256, 0, stream>>>(ptmp, cls, outb);
    }

    const int ROWS = BATCH * SEQ; // 12608

    for (int l = 0; l < NLAYER; l++) {
        // --- ln1 (fp32 only) ---
        layernorm_kernel<<<ROWS, 256, 0, stream>>>(outb, ln1g + l * DIM, ln1b + l * DIM,
                                                   xln, nullptr, nullptr);

        // --- q/k/v per-head projections (SIMT, Z=12 heads) ---
        const float* Ws[3] = { Wq, Wk, Wv };
        const float* bs[3] = { bq, bk, bv };
        float* Cs[3] = { q, k, v };
        for (int t = 0; t < 3; t++) {
            GemmArgs a = {};
            a.A = xln; a.lda = DIM; a.sA1 = DH; a.sA2 = 0;
            a.B = Ws[t] + (long long)l * NHEAD * DH * DH; a.ldb = DH; a.sB1 = (long long)DH * DH; a.sB2 = 0;
            a.C = Cs[t]; a.ldc = DIM; a.sC1 = DH; a.sC2 = 0;
            a.bias = bs[t] + (long long)l * NHEAD * DH; a.sb1 = DH; a.sb2 = 0;
            a.R = nullptr;
            a.M = ROWS; a.N = DH; a.K = DH; a.alpha = 1.0f; a.epi = 0; a.z2 = 1; a.Z = NHEAD;
            launch_gemm(a, true, stream);
        }

        // --- attention scores (SIMT, Z=768) ---
        {
            GemmArgs a = {};
            a.A = q; a.lda = DIM; a.sA1 = SD; a.sA2 = DH;
            a.B = k; a.ldb = DIM; a.sB1 = SD; a.sB2 = DH;
            a.C = att; a.ldc = SEQ; a.sC1 = (long long)NHEAD * SS; a.sC2 = SS;
            a.bias = nullptr; a.R = nullptr;
            a.M = SEQ; a.N = SEQ; a.K = DH; a.alpha = 0.125f; a.epi = 0;
            a.z2 = NHEAD; a.Z = BATCH * NHEAD;
            launch_gemm(a, true, stream);
        }
        softmax_kernel<<<BATCH * NHEAD * SEQ, 256, 0, stream>>>(att, SEQ);

        // --- AV + residual (SIMT, Z=768) ---
        {
            GemmArgs a = {};
            a.A = att; a.lda = SEQ; a.sA1 = (long long)NHEAD * SS; a.sA2 = SS;
            a.B = v; a.ldb = DIM; a.sB1 = SD; a.sB2 = DH;
            a.C = outb; a.ldc = DIM; a.sC1 = SD; a.sC2 = DH;
            a.bias = nullptr;
            a.R = outb; a.sR1 = SD; a.sR2 = DH;
            a.M = SEQ; a.N = DH; a.K = SEQ; a.alpha = 1.0f; a.epi = 0;
            a.z2 = NHEAD; a.Z = BATCH * NHEAD;
            launch_gemm(a, false, stream);
        }

        // --- ln2 (bf16 planes for MLP1) ---
        layernorm_kernel<<<ROWS, 256, 0, stream>>>(outb, ln2g + l * DIM, ln2b + l * DIM,
                                                   nullptr, xh, xl);

        // --- MLP1 + GELU (mma) -> bf16 planes ---
        launch_mma(xh, xl, DIM,
                   w1h + (long long)l * MLPD * DIM, w1l + (long long)l * MLPD * DIM, DIM,
                   nullptr, mh, ml, MLPD,
                   b1 + (long long)l * MLPD, nullptr, ROWS, MLPD, DIM, 1, stream);
        // --- MLP2 + residual (mma) -> fp32 ---
        launch_mma(mh, ml, MLPD,
                   w2h + (long long)l * DIM * MLPD, w2l + (long long)l * DIM * MLPD, MLPD,
                   outb, nullptr, nullptr, DIM,
                   b2 + (long long)l * DIM, outb, ROWS, DIM, MLPD, 0, stream);
    }

    // --- head: out_final = out[:,0,:] @ Wh^T + bh (SIMT) ---
    {
        GemmArgs a = {};
        a.A = outb; a.lda = (int)SD; a.sA1 = 0; a.sA2 = 0;
        a.B = Wh; a.ldb = DIM; a.sB1 = 0; a.sB2 = 0;
        a.C = out_final; a.ldc = OUTD; a.sC1 = 0; a.sC2 = 0;
        a.bias = bh; a.sb1 = 0; a.sb2 = 0;
        a.R = nullptr;
        a.M = BATCH; a.N = OUTD; a.K = DIM; a.alpha = 1.0f; a.epi = 0; a.z2 = 1; a.Z = 1;
        launch_gemm(a, true, stream);
    }
}

// round 4
// speedup vs baseline: 3.3864x; 1.1033x over previous
#include <cuda_runtime.h>
#include <cuda_bf16.h>
#include <cstdint>

// ---------------- problem constants ----------------
#define BATCH 64
#define SEQ 197
#define NPATCH 196
#define DIM 768
#define NHEAD 12
#define DH 64
#define MLPD 3072
#define OUTD 1000
#define NLAYER 12
#define ALD 224                 // padded attention row length (K must be mult of 32)

// ---------------- scratch (static device globals; no allocation) ----------------
__device__ float g_out[(long long)BATCH * SEQ * DIM];          // residual stream
__device__ float g_att[(long long)BATCH * NHEAD * SEQ * ALD];  // attention scores fp32
__device__ float g_ptmp[(long long)BATCH * NPATCH * DIM];      // patch-embed fp32 out

// bf16 hi/lo planes
__device__ __nv_bfloat16 g_ph[(long long)BATCH * NPATCH * DIM];   // patches
__device__ __nv_bfloat16 g_pl[(long long)BATCH * NPATCH * DIM];
__device__ __nv_bfloat16 g_xh[(long long)BATCH * SEQ * DIM];      // ln out
__device__ __nv_bfloat16 g_xl[(long long)BATCH * SEQ * DIM];
__device__ __nv_bfloat16 g_mh[(long long)BATCH * SEQ * MLPD];     // mlp hidden
__device__ __nv_bfloat16 g_ml[(long long)BATCH * SEQ * MLPD];
__device__ __nv_bfloat16 g_qh[(long long)BATCH * SEQ * DIM];
__device__ __nv_bfloat16 g_ql[(long long)BATCH * SEQ * DIM];
__device__ __nv_bfloat16 g_kh[(long long)BATCH * SEQ * DIM];
__device__ __nv_bfloat16 g_kl[(long long)BATCH * SEQ * DIM];
__device__ __nv_bfloat16 g_vth[(long long)BATCH * NHEAD * DH * ALD];  // V^T planes
__device__ __nv_bfloat16 g_vtl[(long long)BATCH * NHEAD * DH * ALD];
__device__ __nv_bfloat16 g_ath[(long long)BATCH * NHEAD * SEQ * ALD]; // att prob planes
__device__ __nv_bfloat16 g_atl[(long long)BATCH * NHEAD * SEQ * ALD];
__device__ __nv_bfloat16 g_wph[(long long)DIM * DIM];             // Wp
__device__ __nv_bfloat16 g_wpl[(long long)DIM * DIM];
__device__ __nv_bfloat16 g_w1h[(long long)NLAYER * MLPD * DIM];   // W1
__device__ __nv_bfloat16 g_w1l[(long long)NLAYER * MLPD * DIM];
__device__ __nv_bfloat16 g_w2h[(long long)NLAYER * DIM * MLPD];   // W2
__device__ __nv_bfloat16 g_w2l[(long long)NLAYER * DIM * MLPD];
__device__ __nv_bfloat16 g_wqh[(long long)NLAYER * NHEAD * DH * DH];
__device__ __nv_bfloat16 g_wql[(long long)NLAYER * NHEAD * DH * DH];
__device__ __nv_bfloat16 g_wkh[(long long)NLAYER * NHEAD * DH * DH];
__device__ __nv_bfloat16 g_wkl[(long long)NLAYER * NHEAD * DH * DH];
__device__ __nv_bfloat16 g_wvh[(long long)NLAYER * NHEAD * DH * DH];
__device__ __nv_bfloat16 g_wvl[(long long)NLAYER * NHEAD * DH * DH];

// ---------------- helpers ----------------
__device__ __forceinline__ uint32_t smem_u32(const void* p) {
    uint32_t a;
    asm("{ .reg .u64 t; cvta.to.shared.u64 t, %1; cvt.u32.u64 %0, t; }" : "=r"(a) : "l"(p));
    return a;
}

__device__ __forceinline__ void bf16_split(float x, __nv_bfloat16& h, __nv_bfloat16& l) {
    h = __float2bfloat16_rn(x);
    l = __float2bfloat16_rn(x - __bfloat162float(h));
}

__device__ __forceinline__ void ldm4(uint32_t* r, uint32_t addr) {
    asm volatile("ldmatrix.sync.aligned.m8n8.x4.shared.b16 {%0,%1,%2,%3}, [%4];"
                 : "=r"(r[0]), "=r"(r[1]), "=r"(r[2]), "=r"(r[3]) : "r"(addr));
}

__device__ __forceinline__ void mma_bf16(float* c, const uint32_t* a, uint32_t b0, uint32_t b1) {
    asm volatile(
        "mma.sync.aligned.m16n8k16.row.col.f32.bf16.bf16.f32 "
        "{%0,%1,%2,%3}, {%4,%5,%6,%7}, {%8,%9}, {%0,%1,%2,%3};"
        : "+f"(c[0]), "+f"(c[1]), "+f"(c[2]), "+f"(c[3])
        : "r"(a[0]), "r"(a[1]), "r"(a[2]), "r"(a[3]), "r"(b0), "r"(b1));
}

__device__ __forceinline__ void cp_async16(uint32_t dst, const void* src, int valid) {
    asm volatile("cp.async.cg.shared.global [%0], [%1], 16, %2;"
                 :: "r"(dst), "l"(src), "r"(valid));
}
__device__ __forceinline__ void cp_commit() { asm volatile("cp.async.commit_group;"); }
__device__ __forceinline__ void cp_wait1() { asm volatile("cp.async.wait_group 1;"); }
__device__ __forceinline__ void cp_wait0() { asm volatile("cp.async.wait_group 0;"); }

// ======================================================================
//  bf16x3 batched NT GEMM:  C[z][M,N] = alpha * A[z] @ B[z]^T (+bias) (+gelu) (+R)
//  z = blockIdx.z decomposed as i1 = z / z2, i2 = z % z2; ptr += i1*s1 + i2*s2.
//  Output: fp32 C (+R), or bf16 hi/lo planes; transC stores planes transposed
//  per batch-n slab: addr = (row/seq)*sCn + col*ldc + (row%seq).
// ======================================================================
#define RSB 80                 // smem row stride bytes (32 bf16 data + pad)
#define PLB (128 * RSB)        // plane bytes = 10240
#define STB (4 * PLB)          // stage bytes (Ahi,Alo,Bhi,Blo) = 40960
#define NSTAGE 3
#define SMEM_MMA (NSTAGE * STB)

__global__ __launch_bounds__(256, 1)
void gemm_bf16x3_kernel(const __nv_bfloat16* __restrict__ Ah, const __nv_bfloat16* __restrict__ Al,
                        long long lda, long long sA1, long long sA2,
                        const __nv_bfloat16* __restrict__ Bh, const __nv_bfloat16* __restrict__ Bl,
                        long long ldb, long long sB1, long long sB2,
                        float* __restrict__ Cf,
                        __nv_bfloat16* __restrict__ Chi, __nv_bfloat16* __restrict__ Clo,
                        long long ldc, long long sC1, long long sC2,
                        const float* __restrict__ bias, long long sb1, long long sb2,
                        const float* __restrict__ R, long long sR1, long long sR2,
                        int M, int N, int K, float alpha, int gelu, int z2,
                        int transC, long long sCn, int seq)
{
    extern __shared__ char sm[];
    uint32_t smb = smem_u32(sm);
    const int tid = threadIdx.x;
    const int lid = tid & 31;
    const int wid = tid >> 5;
    const int wm = wid >> 2;          // 0..1  (64-row slab)
    const int wn = wid & 3;           // 0..3  (32-col slab)
    const int m0 = blockIdx.y * 128;
    const int n0 = blockIdx.x * 128;

    {
        int bz = blockIdx.z;
        int i1 = bz / z2, i2 = bz % z2;
        Ah += i1 * sA1 + i2 * sA2;
        Al += i1 * sA1 + i2 * sA2;
        Bh += i1 * sB1 + i2 * sB2;
        Bl += i1 * sB1 + i2 * sB2;
        if (Cf)  Cf  += i1 * sC1 + i2 * sC2;
        if (Chi) { Chi += i1 * sC1 + i2 * sC2; Clo += i1 * sC1 + i2 * sC2; }
        if (bias) bias += i1 * sb1 + i2 * sb2;
        if (R) R += i1 * sR1 + i2 * sR2;
    }

    const int nch = K >> 5;           // K / 32

    auto load_stage = [&](int s, int chunk) {
        int k0 = chunk << 5;
        uint32_t sbase = smb + s * STB;
        #pragma unroll
        for (int t = 0; t < 8; t++) {
            int id = tid + t * 256;          // 0..2047
            int plane = id >> 9;             // 0..3
            int rc = id & 511;
            int row = rc >> 2;               // 0..127
            int c = rc & 3;                  // 16B chunk
            uint32_t dst = sbase + plane * PLB + row * RSB + c * 16;
            const __nv_bfloat16* src;
            int valid;
            if (plane < 2) {
                int gm = m0 + row;
                int gmc = gm < M ? gm : M - 1;
                src = (plane == 0 ? Ah : Al) + (long long)gmc * lda + k0 + c * 8;
                valid = (gm < M) ? 16 : 0;
            } else {
                int gn = n0 + row;
                int gnc = gn < N ? gn : N - 1;
                src = (plane == 2 ? Bh : Bl) + (long long)gnc * ldb + k0 + c * 8;
                valid = (gn < N) ? 16 : 0;
            }
            cp_async16(dst, src, valid);
        }
        cp_commit();
    };

    float acc[4][4][4];
    #pragma unroll
    for (int i = 0; i < 4; i++)
        #pragma unroll
        for (int j = 0; j < 4; j++)
            #pragma unroll
            for (int r = 0; r < 4; r++) acc[i][j][r] = 0.f;

    load_stage(0, 0);
    if (nch > 1) load_stage(1, 1);

    for (int i = 0; i < nch; i++) {
        if (i == nch - 1) cp_wait0(); else cp_wait1();
        __syncthreads();
        if (i + 2 < nch) load_stage((i + 2) % NSTAGE, i + 2);

        uint32_t sA = smb + (i % NSTAGE) * STB;
        uint32_t sB = sA + 2 * PLB;
        #pragma unroll
        for (int kk = 0; kk < 2; kk++) {
            int kt = kk << 4;
            uint32_t ah[4][4], al[4][4];
            #pragma unroll
            for (int t = 0; t < 4; t++) {
                int m = wm * 64 + t * 16;
                uint32_t row = m + ((lid >> 3) & 1) * 8 + (lid & 7);
                uint32_t koff = kt + (lid >> 4) * 8;
                uint32_t ad = sA + row * RSB + koff * 2;
                ldm4(ah[t], ad);
                ldm4(al[t], ad + PLB);
            }
            uint32_t bh[2][4], bl[2][4];
            #pragma unroll
            for (int p = 0; p < 2; p++) {
                int n = wn * 32 + p * 16;
                uint32_t row = n + (lid >> 4) * 8 + (lid & 7);
                uint32_t koff = kt + ((lid >> 3) & 1) * 8;
                uint32_t bd = sB + row * RSB + koff * 2;
                ldm4(bh[p], bd);
                ldm4(bl[p], bd + PLB);
            }
            #pragma unroll
            for (int t = 0; t < 4; t++) {
                #pragma unroll
                for (int j = 0; j < 4; j++) {
                    uint32_t b0h = bh[j >> 1][(j & 1) * 2], b1h = bh[j >> 1][(j & 1) * 2 + 1];
                    uint32_t b0l = bl[j >> 1][(j & 1) * 2], b1l = bl[j >> 1][(j & 1) * 2 + 1];
                    mma_bf16(acc[t][j], ah[t], b0h, b1h);
                    mma_bf16(acc[t][j], al[t], b0h, b1h);
                    mma_bf16(acc[t][j], ah[t], b0l, b1l);
                }
            }
        }
        __syncthreads();
    }

    // ---- epilogue ----
    #pragma unroll
    for (int t = 0; t < 4; t++) {
        #pragma unroll
        for (int j = 0; j < 4; j++) {
            int col = n0 + wn * 32 + j * 8 + (lid & 3) * 2;
            #pragma unroll
            for (int h = 0; h < 2; h++) {
                int row = m0 + wm * 64 + t * 16 + (lid >> 2) + h * 8;
                if (row >= M) continue;
                #pragma unroll
                for (int e = 0; e < 2; e++) {
                    int c = col + e;
                    if (c >= N) continue;
                    float v = acc[t][j][h * 2 + e] * alpha;
                    if (bias) v += bias[c];
                    if (gelu) v = 0.5f * v * (1.0f + erff(v * 0.70710678118654752f));
                    if (Cf) {
                        long long base = (long long)row * ldc + c;
                        float r = R ? R[base] : 0.f;
                        Cf[base] = v + r;
                    } else if (!transC) {
                        long long base = (long long)row * ldc + c;
                        __nv_bfloat16 hh, ll;
                        bf16_split(v, hh, ll);
                        Chi[base] = hh;
                        Clo[base] = ll;
                    } else {
                        int nb = row / seq, s = row % seq;
                        long long base = (long long)nb * sCn + (long long)c * ldc + s;
                        __nv_bfloat16 hh, ll;
                        bf16_split(v, hh, ll);
                        Chi[base] = hh;
                        Clo[base] = ll;
                    }
                }
            }
        }
    }
}

// ======================================================================
//  small kernels
// ======================================================================
__global__ void zero_bf16_kernel(__nv_bfloat16* __restrict__ p, long long n) {
    long long i = (long long)blockIdx.x * 256 + threadIdx.x;
    if (i < n) p[i] = __float2bfloat16(0.f);
}

__global__ void split_kernel(const float* __restrict__ x, __nv_bfloat16* __restrict__ h,
                             __nv_bfloat16* __restrict__ l, long long n) {
    long long i = ((long long)blockIdx.x * 256 + threadIdx.x) * 4;
    if (i >= n) return;
    float4 v = *(const float4*)(x + i);
    __nv_bfloat16 hh, ll;
    bf16_split(v.x, hh, ll); h[i] = hh; l[i] = ll;
    bf16_split(v.y, hh, ll); h[i + 1] = hh; l[i + 1] = ll;
    bf16_split(v.z, hh, ll); h[i + 2] = hh; l[i + 2] = ll;
    bf16_split(v.w, hh, ll); h[i + 3] = hh; l[i + 3] = ll;
}

__global__ void patchify_kernel(const float* __restrict__ x,
                                __nv_bfloat16* __restrict__ ph, __nv_bfloat16* __restrict__ pl) {
    long long idx = (long long)blockIdx.x * 256 + threadIdx.x;
    const long long total = (long long)BATCH * NPATCH * DIM;
    if (idx >= total) return;
    int e = (int)(idx % DIM);
    long long r = idx / DIM;
    int p = (int)(r % NPATCH);
    int n = (int)(r / NPATCH);
    int c = e / 256;
    int hw = e % 256;
    int hi = hw / 16, wi = hw % 16;
    int pi = p / 14, pj = p % 14;
    float v = x[(((long long)n * 3 + c) * 224 + (pi * 16 + hi)) * 224 + (pj * 16 + wi)];
    __nv_bfloat16 hh, ll;
    bf16_split(v, hh, ll);
    ph[idx] = hh; pl[idx] = ll;
}

__global__ void assemble_kernel(const float* __restrict__ tmp, const float* __restrict__ cls,
                                float* __restrict__ out) {
    long long idx = (long long)blockIdx.x * 256 + threadIdx.x;
    const long long total = (long long)BATCH * SEQ * DIM;
    if (idx >= total) return;
    int d = (int)(idx % DIM);
    long long r = idx / DIM;
    int s = (int)(r % SEQ);
    int n = (int)(r / SEQ);
    float v = (s == 0) ? cls[d] : tmp[((long long)n * NPATCH + (s - 1)) * DIM + d];
    float pe;
    if ((s & 1) == 0) pe = sinf((float)s / powf(10000.0f, (float)d / (float)DIM));
    else              pe = cosf((float)s / powf(10000.0f, (float)(d - 1) / (float)DIM));
    out[idx] = v + pe;
}

// layernorm -> bf16 hi/lo planes
__global__ void layernorm_kernel(const float* __restrict__ x, const float* __restrict__ g,
                                 const float* __restrict__ b,
                                 __nv_bfloat16* __restrict__ yh, __nv_bfloat16* __restrict__ yl) {
    long long row = blockIdx.x;
    const float* p = x + row * DIM;
    __shared__ float s1[256], s2[256];
    int t = threadIdx.x;
    float a = 0.f, a2 = 0.f;
    for (int j = t; j < DIM; j += 256) { float v = p[j]; a += v; a2 += v * v; }
    s1[t] = a; s2[t] = a2; __syncthreads();
    for (int s = 128; s > 0; s >>= 1) {
        if (t < s) { s1[t] += s1[t + s]; s2[t] += s2[t + s]; }
        __syncthreads();
    }
    float mu = s1[0] * (1.0f / DIM);
    float var = s2[0] * (1.0f / DIM) - mu * mu;
    float inv = rsqrtf(var + 1e-5f);
    for (int j = t; j < DIM; j += 256) {
        float v = (p[j] - mu) * inv * g[j] + b[j];
        __nv_bfloat16 hh, ll;
        bf16_split(v, hh, ll);
        yh[row * DIM + j] = hh; yl[row * DIM + j] = ll;
    }
}

// softmax over one score row (197 valid, pad to 224 with zeros) -> bf16 planes
__global__ void softmax_planes_kernel(const float* __restrict__ att,
                                      __nv_bfloat16* __restrict__ oh,
                                      __nv_bfloat16* __restrict__ ol) {
    long long row = blockIdx.x;
    const float* p = att + row * ALD;
    int t = threadIdx.x;                  // 256
    float v = (t < SEQ) ? p[t] : -1e30f;
    __shared__ float red[256];
    red[t] = v; __syncthreads();
    for (int s = 128; s > 0; s >>= 1) { if (t < s) red[t] = fmaxf(red[t], red[t + s]); __syncthreads(); }
    float m = red[0]; __syncthreads();
    float e = (t < SEQ) ? expf(v - m) : 0.f;
    red[t] = e; __syncthreads();
    for (int s = 128; s > 0; s >>= 1) { if (t < s) red[t] += red[t + s]; __syncthreads(); }
    float inv = 1.0f / red[0];
    if (t < ALD) {
        float pr = e * inv;               // 0 in pad region
        __nv_bfloat16 hh, ll;
        bf16_split(pr, hh, ll);
        oh[row * ALD + t] = hh;
        ol[row * ALD + t] = ll;
    }
}

// ======================================================================
//  generic SIMT GEMM (head only)
// ======================================================================
#define BM 64
#define BN 64
#define BK 16

__global__ void gemm_simt_kernel(
    const float* __restrict__ A, int lda,
    const float* __restrict__ B, int ldb,
    float* __restrict__ C, int ldc,
    const float* __restrict__ bias,
    int M, int N, int K)
{
    __shared__ float As[BK][BM];
    __shared__ float Bs[BK][BN];
    int bm = blockIdx.y * BM;
    int bn = blockIdx.x * BN;
    int tid = threadIdx.x;
    int tx = tid % 16, ty = tid / 16;
    float acc[4][4] = {};
    for (int k0 = 0; k0 < K; k0 += BK) {
        #pragma unroll
        for (int i = 0; i < 4; i++) {
            int idx = tid + i * 256;
            int m = idx / BK, kk = idx % BK;
            int gm = bm + m, gk = k0 + kk;
            As[kk][m] = (gm < M && gk < K) ? A[(long long)gm * lda + gk] : 0.f;
        }
        #pragma unroll
        for (int i = 0; i < 4; i++) {
            int idx = tid + i * 256;
            int n = idx / BK, kk = idx % BK;
            int gn = bn + n, gk = k0 + kk;
            Bs[kk][n] = (gn < N && gk < K) ? B[(long long)gn * ldb + gk] : 0.f;
        }
        __syncthreads();
        #pragma unroll
        for (int kk = 0; kk < BK; kk++) {
            float a[4], b[4];
            #pragma unroll
            for (int i = 0; i < 4; i++) a[i] = As[kk][ty * 4 + i];
            #pragma unroll
            for (int j = 0; j < 4; j++) b[j] = Bs[kk][tx * 4 + j];
            #pragma unroll
            for (int i = 0; i < 4; i++)
                #pragma unroll
                for (int j = 0; j < 4; j++)
                    acc[i][j] += a[i] * b[j];
        }
        __syncthreads();
    }
    #pragma unroll
    for (int i = 0; i < 4; i++) {
        int gm = bm + ty * 4 + i;
        if (gm >= M) continue;
        #pragma unroll
        for (int j = 0; j < 4; j++) {
            int gn = bn + tx * 4 + j;
            if (gn >= N) continue;
            C[(long long)gm * ldc + gn] = acc[i][j] + (bias ? bias[gn] : 0.f);
        }
    }
}

// ======================================================================
//  launch helper
// ======================================================================
struct MArgs {
    const __nv_bfloat16 *Ah, *Al; long long lda, sA1, sA2;
    const __nv_bfloat16 *Bh, *Bl; long long ldb, sB1, sB2;
    float* Cf; __nv_bfloat16 *Chi, *Clo; long long ldc, sC1, sC2;
    const float* bias; long long sb1, sb2;
    const float* R; long long sR1, sR2;
    int M, N, K; float alpha; int gelu; int z2; int Z;
    int transC; long long sCn; int seq;
};

static void launch_mma(const MArgs& a, cudaStream_t stream) {
    static bool attr_set = false;
    if (!attr_set) {
        cudaFuncSetAttribute(gemm_bf16x3_kernel,
                             cudaFuncAttributeMaxDynamicSharedMemorySize, SMEM_MMA);
        attr_set = true;
    }
    dim3 grid((a.N + 127) / 128, (a.M + 127) / 128, a.Z);
    gemm_bf16x3_kernel<<<grid, 256, SMEM_MMA, stream>>>(
        a.Ah, a.Al, a.lda, a.sA1, a.sA2,
        a.Bh, a.Bl, a.ldb, a.sB1, a.sB2,
        a.Cf, a.Chi, a.Clo, a.ldc, a.sC1, a.sC2,
        a.bias, a.sb1, a.sb2, a.R, a.sR1, a.sR2,
        a.M, a.N, a.K, a.alpha, a.gelu, a.z2, a.transC, a.sCn, a.seq);
}

// ======================================================================
//  orchestration
// ======================================================================
extern "C" void kernel_launch(void* const* d_in, const int* in_sizes, int n_in,
                              void* d_out, int out_size) {
    (void)in_sizes; (void)n_in; (void)out_size;
    const float* x    = (const float*)d_in[0];
    const float* Wp   = (const float*)d_in[1];
    const float* bp   = (const float*)d_in[2];
    const float* cls  = (const float*)d_in[3];
    const float* ln1g = (const float*)d_in[4];
    const float* ln1b = (const float*)d_in[5];
    const float* Wq   = (const float*)d_in[6];
    const float* bq   = (const float*)d_in[7];
    const float* Wk   = (const float*)d_in[8];
    const float* bk   = (const float*)d_in[9];
    const float* Wv   = (const float*)d_in[10];
    const float* bv   = (const float*)d_in[11];
    const float* ln2g = (const float*)d_in[12];
    const float* ln2b = (const float*)d_in[13];
    const float* W1   = (const float*)d_in[14];
    const float* b1   = (const float*)d_in[15];
    const float* W2   = (const float*)d_in[16];
    const float* b2   = (const float*)d_in[17];
    const float* Wh   = (const float*)d_in[18];
    const float* bh   = (const float*)d_in[19];
    float* out_final  = (float*)d_out;

    float *outb, *att, *ptmp;
    __nv_bfloat16 *ph, *pl, *xh, *xl, *mh, *ml;
    __nv_bfloat16 *qh, *ql, *kh, *kl, *vth, *vtl, *ath, *atl;
    __nv_bfloat16 *wph, *wpl, *w1h, *w1l, *w2h, *w2l;
    __nv_bfloat16 *wqh, *wql, *wkh, *wkl, *wvh, *wvl;
    cudaGetSymbolAddress((void**)&outb, g_out);
    cudaGetSymbolAddress((void**)&att,  g_att);
    cudaGetSymbolAddress((void**)&ptmp, g_ptmp);
    cudaGetSymbolAddress((void**)&ph,   g_ph);
    cudaGetSymbolAddress((void**)&pl,   g_pl);
    cudaGetSymbolAddress((void**)&xh,   g_xh);
    cudaGetSymbolAddress((void**)&xl,   g_xl);
    cudaGetSymbolAddress((void**)&mh,   g_mh);
    cudaGetSymbolAddress((void**)&ml,   g_ml);
    cudaGetSymbolAddress((void**)&qh,   g_qh);
    cudaGetSymbolAddress((void**)&ql,   g_ql);
    cudaGetSymbolAddress((void**)&kh,   g_kh);
    cudaGetSymbolAddress((void**)&kl,   g_kl);
    cudaGetSymbolAddress((void**)&vth,  g_vth);
    cudaGetSymbolAddress((void**)&vtl,  g_vtl);
    cudaGetSymbolAddress((void**)&ath,  g_ath);
    cudaGetSymbolAddress((void**)&atl,  g_atl);
    cudaGetSymbolAddress((void**)&wph,  g_wph);
    cudaGetSymbolAddress((void**)&wpl,  g_wpl);
    cudaGetSymbolAddress((void**)&w1h,  g_w1h);
    cudaGetSymbolAddress((void**)&w1l,  g_w1l);
    cudaGetSymbolAddress((void**)&w2h,  g_w2h);
    cudaGetSymbolAddress((void**)&w2l,  g_w2l);
    cudaGetSymbolAddress((void**)&wqh,  g_wqh);
    cudaGetSymbolAddress((void**)&wql,  g_wql);
    cudaGetSymbolAddress((void**)&wkh,  g_wkh);
    cudaGetSymbolAddress((void**)&wkl,  g_wkl);
    cudaGetSymbolAddress((void**)&wvh,  g_wvh);
    cudaGetSymbolAddress((void**)&wvl,  g_wvl);

    cudaStream_t stream = 0;
    const long long SD = (long long)SEQ * DIM;
    const long long SA = (long long)SEQ * ALD;       // per-(n,h) att slab
    const long long VA = (long long)DH * ALD;        // per-(n,h) vT slab
    const int ROWS = BATCH * SEQ;                    // 12608

    // 0) weight splits + vT pad zero (deterministic every run)
    {
        long long n;
        n = (long long)DIM * DIM;
        split_kernel<<<(unsigned)((n / 4 + 255) / 256), 256, 0, stream>>>(Wp, wph, wpl, n);
        n = (long long)NLAYER * MLPD * DIM;
        split_kernel<<<(unsigned)((n / 4 + 255) / 256), 256, 0, stream>>>(W1, w1h, w1l, n);
        split_kernel<<<(unsigned)((n / 4 + 255) / 256), 256, 0, stream>>>(W2, w2h, w2l, n);
        n = (long long)NLAYER * NHEAD * DH * DH;
        split_kernel<<<(unsigned)((n / 4 + 255) / 256), 256, 0, stream>>>(Wq, wqh, wql, n);
        split_kernel<<<(unsigned)((n / 4 + 255) / 256), 256, 0, stream>>>(Wk, wkh, wkl, n);
        split_kernel<<<(unsigned)((n / 4 + 255) / 256), 256, 0, stream>>>(Wv, wvh, wvl, n);
        n = (long long)BATCH * NHEAD * DH * ALD;
        zero_bf16_kernel<<<(unsigned)((n + 255) / 256), 256, 0, stream>>>(vth, n);
        zero_bf16_kernel<<<(unsigned)((n + 255) / 256), 256, 0, stream>>>(vtl, n);
    }

    // 1) patchify -> bf16 planes
    {
        long long total = (long long)BATCH * NPATCH * DIM;
        patchify_kernel<<<(unsigned)((total + 255) / 256), 256, 0, stream>>>(x, ph, pl);
    }
    // 2) patch embedding (mma): ptmp = patches @ Wp^T + bp
    {
        MArgs a = {};
        a.Ah = ph; a.Al = pl; a.lda = DIM;
        a.Bh = wph; a.Bl = wpl; a.ldb = DIM;
        a.Cf = ptmp; a.ldc = DIM;
        a.bias = bp;
        a.M = BATCH * NPATCH; a.N = DIM; a.K = DIM; a.alpha = 1.f;
        a.z2 = 1; a.Z = 1; a.seq = SEQ;
        launch_mma(a, stream);
    }
    // 3) assemble tokens + cls + positional embedding
    {
        long long total = (long long)BATCH * SEQ * DIM;
        assemble_kernel<<<(unsigned)((total + 255) / 256), 256, 0, stream>>>(ptmp, cls, outb);
    }

    for (int l = 0; l < NLAYER; l++) {
        // --- ln1 -> bf16 planes ---
        layernorm_kernel<<<ROWS, 256, 0, stream>>>(outb, ln1g + l * DIM, ln1b + l * DIM, xh, xl);

        // --- Q, K projections (per-head batch Z=12) -> bf16 planes ---
        const long long WOFF = (long long)l * NHEAD * DH * DH;
        {
            MArgs a = {};
            a.Ah = xh; a.Al = xl; a.lda = DIM; a.sA1 = DH;
            a.Bh = wqh + WOFF; a.Bl = wql + WOFF; a.ldb = DH; a.sB1 = (long long)DH * DH;
            a.Chi = qh; a.Clo = ql; a.ldc = DIM; a.sC1 = DH;
            a.bias = bq + (long long)l * NHEAD * DH; a.sb1 = DH;
            a.M = ROWS; a.N = DH; a.K = DH; a.alpha = 1.f;
            a.z2 = 1; a.Z = NHEAD; a.seq = SEQ;
            launch_mma(a, stream);
            a.Bh = wkh + WOFF; a.Bl = wkl + WOFF;
            a.Chi = kh; a.Clo = kl;
            a.bias = bk + (long long)l * NHEAD * DH;
            launch_mma(a, stream);
        }
        // --- V projection -> transposed planes vT[n][h][o][s] ---
        {
            MArgs a = {};
            a.Ah = xh; a.Al = xl; a.lda = DIM; a.sA1 = DH;
            a.Bh = wvh + WOFF; a.Bl = wvl + WOFF; a.ldb = DH; a.sB1 = (long long)DH * DH;
            a.Chi = vth; a.Clo = vtl; a.ldc = ALD; a.sC1 = VA;   // per-head offset
            a.bias = bv + (long long)l * NHEAD * DH; a.sb1 = DH;
            a.M = ROWS; a.N = DH; a.K = DH; a.alpha = 1.f;
            a.z2 = 1; a.Z = NHEAD; a.seq = SEQ;
            a.transC = 1; a.sCn = (long long)NHEAD * VA;          // per-n slab
            launch_mma(a, stream);
        }

        // --- scores: att[z] = q[z] @ k[z]^T / 8   (Z = n*h = 768) ---
        {
            MArgs a = {};
            a.Ah = qh; a.Al = ql; a.lda = DIM; a.sA1 = SD; a.sA2 = DH;
            a.Bh = kh; a.Bl = kl; a.ldb = DIM; a.sB1 = SD; a.sB2 = DH;
            a.Cf = att; a.ldc = ALD; a.sC1 = (long long)NHEAD * SA; a.sC2 = SA;
            a.M = SEQ; a.N = SEQ; a.K = DH; a.alpha = 0.125f;
            a.z2 = NHEAD; a.Z = BATCH * NHEAD; a.seq = SEQ;
            launch_mma(a, stream);
        }
        // --- softmax -> bf16 prob planes (zero pad to 224) ---
        softmax_planes_kernel<<<BATCH * NHEAD * SEQ, 256, 0, stream>>>(att, ath, atl);

        // --- AV + residual: out[n,:,h] += att[n,h] @ vT[n,h]^T ---
        {
            MArgs a = {};
            a.Ah = ath; a.Al = atl; a.lda = ALD; a.sA1 = (long long)NHEAD * SA; a.sA2 = SA;
            a.Bh = vth; a.Bl = vtl; a.ldb = ALD; a.sB1 = (long long)NHEAD * VA; a.sB2 = VA;
            a.Cf = outb; a.ldc = DIM; a.sC1 = SD; a.sC2 = DH;
            a.R = outb; a.sR1 = SD; a.sR2 = DH;
            a.M = SEQ; a.N = DH; a.K = ALD; a.alpha = 1.f;
            a.z2 = NHEAD; a.Z = BATCH * NHEAD; a.seq = SEQ;
            launch_mma(a, stream);
        }

        // --- ln2 -> bf16 planes ---
        layernorm_kernel<<<ROWS, 256, 0, stream>>>(outb, ln2g + l * DIM, ln2b + l * DIM, xh, xl);

        // --- MLP1 + GELU (mma) -> bf16 planes ---
        {
            MArgs a = {};
            a.Ah = xh; a.Al = xl; a.lda = DIM;
            a.Bh = w1h + (long long)l * MLPD * DIM; a.Bl = w1l + (long long)l * MLPD * DIM; a.ldb = DIM;
            a.Chi = mh; a.Clo = ml; a.ldc = MLPD;
            a.bias = b1 + (long long)l * MLPD;
            a.M = ROWS; a.N = MLPD; a.K = DIM; a.alpha = 1.f; a.gelu = 1;
            a.z2 = 1; a.Z = 1; a.seq = SEQ;
            launch_mma(a, stream);
        }
        // --- MLP2 + residual (mma) -> fp32 ---
        {
            MArgs a = {};
            a.Ah = mh; a.Al = ml; a.lda = MLPD;
            a.Bh = w2h + (long long)l * DIM * MLPD; a.Bl = w2l + (long long)l * DIM * MLPD; a.ldb = MLPD;
            a.Cf = outb; a.ldc = DIM;
            a.bias = b2 + (long long)l * DIM;
            a.R = outb;
            a.M = ROWS; a.N = DIM; a.K = MLPD; a.alpha = 1.f;
            a.z2 = 1; a.Z = 1; a.seq = SEQ;
            launch_mma(a, stream);
        }
    }

    // --- head: out_final = out[:,0,:] @ Wh^T + bh (SIMT, tiny) ---
    {
        dim3 grid((OUTD + BN - 1) / BN, (BATCH + BM - 1) / BM, 1);
        gemm_simt_kernel<<<grid, 256, 0, stream>>>(
            outb, (int)SD, Wh, DIM, out_final, OUTD, bh, BATCH, OUTD, DIM);
    }
}

// round 5
// speedup vs baseline: 7.0667x; 2.0868x over previous
#include <cuda_runtime.h>
#include <cuda_fp16.h>
#include <cstdint>

// ---------------- problem constants ----------------
#define BATCH 64
#define SEQ 197
#define NPATCH 196
#define DIM 768
#define NHEAD 12
#define DH 64
#define MLPD 3072
#define OUTD 1000
#define NLAYER 12
#define ALD 224                 // padded attention row length (mult of 32)

// ---------------- scratch (static device globals; no allocation) ----------------
__device__ float g_out[(long long)BATCH * SEQ * DIM];          // residual stream
__device__ float g_att[(long long)BATCH * NHEAD * SEQ * ALD];  // attention scores fp32
__device__ float g_ptmp[(long long)BATCH * NPATCH * DIM];      // patch-embed fp32 out

// fp16 activation / weight buffers
__device__ __half g_ph[(long long)BATCH * NPATCH * DIM];   // patches
__device__ __half g_xh[(long long)BATCH * SEQ * DIM];      // ln out
__device__ __half g_mh[(long long)BATCH * SEQ * MLPD];     // mlp hidden
__device__ __half g_qh[(long long)BATCH * SEQ * DIM];
__device__ __half g_kh[(long long)BATCH * SEQ * DIM];
__device__ __half g_vth[(long long)BATCH * NHEAD * DH * ALD];  // V^T
__device__ __half g_ath[(long long)BATCH * NHEAD * SEQ * ALD]; // att probs
__device__ __half g_wph[(long long)DIM * DIM];
__device__ __half g_w1h[(long long)NLAYER * MLPD * DIM];
__device__ __half g_w2h[(long long)NLAYER * DIM * MLPD];
__device__ __half g_wqh[(long long)NLAYER * NHEAD * DH * DH];
__device__ __half g_wkh[(long long)NLAYER * NHEAD * DH * DH];
__device__ __half g_wvh[(long long)NLAYER * NHEAD * DH * DH];

// ---------------- helpers ----------------
__device__ __forceinline__ uint32_t smem_u32(const void* p) {
    uint32_t a;
    asm("{ .reg .u64 t; cvta.to.shared.u64 t, %1; cvt.u32.u64 %0, t; }" : "=r"(a) : "l"(p));
    return a;
}

__device__ __forceinline__ void ldm4(uint32_t* r, uint32_t addr) {
    asm volatile("ldmatrix.sync.aligned.m8n8.x4.shared.b16 {%0,%1,%2,%3}, [%4];"
                 : "=r"(r[0]), "=r"(r[1]), "=r"(r[2]), "=r"(r[3]) : "r"(addr));
}

__device__ __forceinline__ void mma_fp16(float* c, const uint32_t* a, uint32_t b0, uint32_t b1) {
    asm volatile(
        "mma.sync.aligned.m16n8k16.row.col.f32.f16.f16.f32 "
        "{%0,%1,%2,%3}, {%4,%5,%6,%7}, {%8,%9}, {%0,%1,%2,%3};"
        : "+f"(c[0]), "+f"(c[1]), "+f"(c[2]), "+f"(c[3])
        : "r"(a[0]), "r"(a[1]), "r"(a[2]), "r"(a[3]), "r"(b0), "r"(b1));
}

__device__ __forceinline__ void cp_async16(uint32_t dst, const void* src, int valid) {
    asm volatile("cp.async.cg.shared.global [%0], [%1], 16, %2;"
                 :: "r"(dst), "l"(src), "r"(valid));
}
__device__ __forceinline__ void cp_commit() { asm volatile("cp.async.commit_group;"); }
__device__ __forceinline__ void cp_wait1() { asm volatile("cp.async.wait_group 1;"); }
__device__ __forceinline__ void cp_wait0() { asm volatile("cp.async.wait_group 0;"); }

// ======================================================================
//  fp16 batched NT GEMM:  C[z][M,N] = alpha * A[z] @ B[z]^T (+bias) (+gelu) (+R)
//  z = blockIdx.z: i1 = z / z2, i2 = z % z2; ptr += i1*s1 + i2*s2.
//  Output fp32 (+R) or fp16; transC stores per batch-n slab transposed:
//  addr = (row/seq)*sCn + col*ldc + (row%seq).
// ======================================================================
#define RSB 80                 // smem row stride bytes (32 fp16 = 64B data + pad)
#define PLB (128 * RSB)        // plane bytes = 10240
#define STB (2 * PLB)          // stage bytes (A, B) = 20480
#define NSTAGE 3
#define SMEM_MMA (NSTAGE * STB)

__global__ __launch_bounds__(256, 2)
void gemm_fp16_kernel(const __half* __restrict__ Ah, long long lda, long long sA1, long long sA2,
                      const __half* __restrict__ Bh, long long ldb, long long sB1, long long sB2,
                      float* __restrict__ Cf, __half* __restrict__ Ch,
                      long long ldc, long long sC1, long long sC2,
                      const float* __restrict__ bias, long long sb1, long long sb2,
                      const float* __restrict__ R, long long sR1, long long sR2,
                      int M, int N, int K, float alpha, int gelu, int z2,
                      int transC, long long sCn, int seq)
{
    extern __shared__ char sm[];
    uint32_t smb = smem_u32(sm);
    const int tid = threadIdx.x;
    const int lid = tid & 31;
    const int wid = tid >> 5;
    const int wm = wid >> 2;          // 0..1
    const int wn = wid & 3;           // 0..3
    const int m0 = blockIdx.y * 128;
    const int n0 = blockIdx.x * 128;

    {
        int bz = blockIdx.z;
        int i1 = bz / z2, i2 = bz % z2;
        Ah += i1 * sA1 + i2 * sA2;
        Bh += i1 * sB1 + i2 * sB2;
        if (Cf) Cf += i1 * sC1 + i2 * sC2;
        if (Ch) Ch += i1 * sC1 + i2 * sC2;
        if (bias) bias += i1 * sb1 + i2 * sb2;
        if (R) R += i1 * sR1 + i2 * sR2;
    }

    const int nch = K >> 5;           // K / 32

    auto load_stage = [&](int s, int chunk) {
        int k0 = chunk << 5;
        uint32_t sbase = smb + s * STB;
        #pragma unroll
        for (int t = 0; t < 4; t++) {
            int id = tid + t * 256;          // 0..1023
            int plane = id >> 9;             // 0:A 1:B
            int rc = id & 511;
            int row = rc >> 2;               // 0..127
            int c = rc & 3;                  // 16B chunk
            uint32_t dst = sbase + plane * PLB + row * RSB + c * 16;
            const __half* src;
            int valid;
            if (plane == 0) {
                int gm = m0 + row;
                int gmc = gm < M ? gm : M - 1;
                src = Ah + (long long)gmc * lda + k0 + c * 8;
                valid = (gm < M) ? 16 : 0;
            } else {
                int gn = n0 + row;
                int gnc = gn < N ? gn : N - 1;
                src = Bh + (long long)gnc * ldb + k0 + c * 8;
                valid = (gn < N) ? 16 : 0;
            }
            cp_async16(dst, src, valid);
        }
        cp_commit();
    };

    float acc[4][4][4];
    #pragma unroll
    for (int i = 0; i < 4; i++)
        #pragma unroll
        for (int j = 0; j < 4; j++)
            #pragma unroll
            for (int r = 0; r < 4; r++) acc[i][j][r] = 0.f;

    load_stage(0, 0);
    if (nch > 1) load_stage(1, 1);

    for (int i = 0; i < nch; i++) {
        if (i == nch - 1) cp_wait0(); else cp_wait1();
        __syncthreads();
        if (i + 2 < nch) load_stage((i + 2) % NSTAGE, i + 2);

        uint32_t sA = smb + (i % NSTAGE) * STB;
        uint32_t sB = sA + PLB;
        #pragma unroll
        for (int kk = 0; kk < 2; kk++) {
            int kt = kk << 4;
            uint32_t af[4][4];
            #pragma unroll
            for (int t = 0; t < 4; t++) {
                int m = wm * 64 + t * 16;
                uint32_t row = m + ((lid >> 3) & 1) * 8 + (lid & 7);
                uint32_t koff = kt + (lid >> 4) * 8;
                ldm4(af[t], sA + row * RSB + koff * 2);
            }
            uint32_t bf[2][4];
            #pragma unroll
            for (int p = 0; p < 2; p++) {
                int n = wn * 32 + p * 16;
                uint32_t row = n + (lid >> 4) * 8 + (lid & 7);
                uint32_t koff = kt + ((lid >> 3) & 1) * 8;
                ldm4(bf[p], sB + row * RSB + koff * 2);
            }
            #pragma unroll
            for (int t = 0; t < 4; t++) {
                #pragma unroll
                for (int j = 0; j < 4; j++) {
                    uint32_t b0 = bf[j >> 1][(j & 1) * 2], b1 = bf[j >> 1][(j & 1) * 2 + 1];
                    mma_fp16(acc[t][j], af[t], b0, b1);
                }
            }
        }
        __syncthreads();
    }

    // ---- epilogue ----
    #pragma unroll
    for (int t = 0; t < 4; t++) {
        #pragma unroll
        for (int j = 0; j < 4; j++) {
            int col = n0 + wn * 32 + j * 8 + (lid & 3) * 2;
            #pragma unroll
            for (int h = 0; h < 2; h++) {
                int row = m0 + wm * 64 + t * 16 + (lid >> 2) + h * 8;
                if (row >= M) continue;
                #pragma unroll
                for (int e = 0; e < 2; e++) {
                    int c = col + e;
                    if (c >= N) continue;
                    float v = acc[t][j][h * 2 + e] * alpha;
                    if (bias) v += bias[c];
                    if (gelu) v = 0.5f * v * (1.0f + erff(v * 0.70710678118654752f));
                    if (Cf) {
                        long long base = (long long)row * ldc + c;
                        float r = R ? R[base] : 0.f;
                        Cf[base] = v + r;
                    } else if (!transC) {
                        Ch[(long long)row * ldc + c] = __float2half_rn(v);
                    } else {
                        int nb = row / seq, s = row % seq;
                        Ch[(long long)nb * sCn + (long long)c * ldc + s] = __float2half_rn(v);
                    }
                }
            }
        }
    }
}

// ======================================================================
//  small kernels
// ======================================================================
__global__ void zero_fp16_kernel(__half* __restrict__ p, long long n) {
    long long i = (long long)blockIdx.x * 256 + threadIdx.x;
    if (i < n) p[i] = __float2half(0.f);
}

__global__ void cvt_kernel(const float* __restrict__ x, __half* __restrict__ h, long long n) {
    long long i = ((long long)blockIdx.x * 256 + threadIdx.x) * 4;
    if (i >= n) return;
    float4 v = *(const float4*)(x + i);
    h[i]     = __float2half_rn(v.x);
    h[i + 1] = __float2half_rn(v.y);
    h[i + 2] = __float2half_rn(v.z);
    h[i + 3] = __float2half_rn(v.w);
}

__global__ void patchify_kernel(const float* __restrict__ x, __half* __restrict__ ph) {
    long long idx = (long long)blockIdx.x * 256 + threadIdx.x;
    const long long total = (long long)BATCH * NPATCH * DIM;
    if (idx >= total) return;
    int e = (int)(idx % DIM);
    long long r = idx / DIM;
    int p = (int)(r % NPATCH);
    int n = (int)(r / NPATCH);
    int c = e / 256;
    int hw = e % 256;
    int hi = hw / 16, wi = hw % 16;
    int pi = p / 14, pj = p % 14;
    ph[idx] = __float2half_rn(
        x[(((long long)n * 3 + c) * 224 + (pi * 16 + hi)) * 224 + (pj * 16 + wi)]);
}

__global__ void assemble_kernel(const float* __restrict__ tmp, const float* __restrict__ cls,
                                float* __restrict__ out) {
    long long idx = (long long)blockIdx.x * 256 + threadIdx.x;
    const long long total = (long long)BATCH * SEQ * DIM;
    if (idx >= total) return;
    int d = (int)(idx % DIM);
    long long r = idx / DIM;
    int s = (int)(r % SEQ);
    int n = (int)(r / SEQ);
    float v = (s == 0) ? cls[d] : tmp[((long long)n * NPATCH + (s - 1)) * DIM + d];
    float pe;
    if ((s & 1) == 0) pe = sinf((float)s / powf(10000.0f, (float)d / (float)DIM));
    else              pe = cosf((float)s / powf(10000.0f, (float)(d - 1) / (float)DIM));
    out[idx] = v + pe;
}

// layernorm -> fp16
__global__ void layernorm_kernel(const float* __restrict__ x, const float* __restrict__ g,
                                 const float* __restrict__ b, __half* __restrict__ yh) {
    long long row = blockIdx.x;
    const float* p = x + row * DIM;
    __shared__ float s1[256], s2[256];
    int t = threadIdx.x;
    float a = 0.f, a2 = 0.f;
    for (int j = t; j < DIM; j += 256) { float v = p[j]; a += v; a2 += v * v; }
    s1[t] = a; s2[t] = a2; __syncthreads();
    for (int s = 128; s > 0; s >>= 1) {
        if (t < s) { s1[t] += s1[t + s]; s2[t] += s2[t + s]; }
        __syncthreads();
    }
    float mu = s1[0] * (1.0f / DIM);
    float var = s2[0] * (1.0f / DIM) - mu * mu;
    float inv = rsqrtf(var + 1e-5f);
    for (int j = t; j < DIM; j += 256)
        yh[row * DIM + j] = __float2half_rn((p[j] - mu) * inv * g[j] + b[j]);
}

// softmax over one score row (197 valid, pad to 224 with zeros) -> fp16
__global__ void softmax_kernel(const float* __restrict__ att, __half* __restrict__ oh) {
    long long row = blockIdx.x;
    const float* p = att + row * ALD;
    int t = threadIdx.x;                  // 256
    float v = (t < SEQ) ? p[t] : -1e30f;
    __shared__ float red[256];
    red[t] = v; __syncthreads();
    for (int s = 128; s > 0; s >>= 1) { if (t < s) red[t] = fmaxf(red[t], red[t + s]); __syncthreads(); }
    float m = red[0]; __syncthreads();
    float e = (t < SEQ) ? expf(v - m) : 0.f;
    red[t] = e; __syncthreads();
    for (int s = 128; s > 0; s >>= 1) { if (t < s) red[t] += red[t + s]; __syncthreads(); }
    float inv = 1.0f / red[0];
    if (t < ALD) oh[row * ALD + t] = __float2half_rn(e * inv);
}

// ======================================================================
//  generic SIMT GEMM (head only)
// ======================================================================
#define BM 64
#define BN 64
#define BK 16

__global__ void gemm_simt_kernel(
    const float* __restrict__ A, int lda,
    const float* __restrict__ B, int ldb,
    float* __restrict__ C, int ldc,
    const float* __restrict__ bias,
    int M, int N, int K)
{
    __shared__ float As[BK][BM];
    __shared__ float Bs[BK][BN];
    int bm = blockIdx.y * BM;
    int bn = blockIdx.x * BN;
    int tid = threadIdx.x;
    int tx = tid % 16, ty = tid / 16;
    float acc[4][4] = {};
    for (int k0 = 0; k0 < K; k0 += BK) {
        #pragma unroll
        for (int i = 0; i < 4; i++) {
            int idx = tid + i * 256;
            int m = idx / BK, kk = idx % BK;
            int gm = bm + m, gk = k0 + kk;
            As[kk][m] = (gm < M && gk < K) ? A[(long long)gm * lda + gk] : 0.f;
        }
        #pragma unroll
        for (int i = 0; i < 4; i++) {
            int idx = tid + i * 256;
            int n = idx / BK, kk = idx % BK;
            int gn = bn + n, gk = k0 + kk;
            Bs[kk][n] = (gn < N && gk < K) ? B[(long long)gn * ldb + gk] : 0.f;
        }
        __syncthreads();
        #pragma unroll
        for (int kk = 0; kk < BK; kk++) {
            float a[4], b[4];
            #pragma unroll
            for (int i = 0; i < 4; i++) a[i] = As[kk][ty * 4 + i];
            #pragma unroll
            for (int j = 0; j < 4; j++) b[j] = Bs[kk][tx * 4 + j];
            #pragma unroll
            for (int i = 0; i < 4; i++)
                #pragma unroll
                for (int j = 0; j < 4; j++)
                    acc[i][j] += a[i] * b[j];
        }
        __syncthreads();
    }
    #pragma unroll
    for (int i = 0; i < 4; i++) {
        int gm = bm + ty * 4 + i;
        if (gm >= M) continue;
        #pragma unroll
        for (int j = 0; j < 4; j++) {
            int gn = bn + tx * 4 + j;
            if (gn >= N) continue;
            C[(long long)gm * ldc + gn] = acc[i][j] + (bias ? bias[gn] : 0.f);
        }
    }
}

// ======================================================================
//  launch helper
// ======================================================================
struct MArgs {
    const __half *Ah; long long lda, sA1, sA2;
    const __half *Bh; long long ldb, sB1, sB2;
    float* Cf; __half* Ch; long long ldc, sC1, sC2;
    const float* bias; long long sb1, sb2;
    const float* R; long long sR1, sR2;
    int M, N, K; float alpha; int gelu; int z2; int Z;
    int transC; long long sCn; int seq;
};

static void launch_mma(const MArgs& a, cudaStream_t stream) {
    static bool attr_set = false;
    if (!attr_set) {
        cudaFuncSetAttribute(gemm_fp16_kernel,
                             cudaFuncAttributeMaxDynamicSharedMemorySize, SMEM_MMA);
        attr_set = true;
    }
    dim3 grid((a.N + 127) / 128, (a.M + 127) / 128, a.Z);
    gemm_fp16_kernel<<<grid, 256, SMEM_MMA, stream>>>(
        a.Ah, a.lda, a.sA1, a.sA2,
        a.Bh, a.ldb, a.sB1, a.sB2,
        a.Cf, a.Ch, a.ldc, a.sC1, a.sC2,
        a.bias, a.sb1, a.sb2, a.R, a.sR1, a.sR2,
        a.M, a.N, a.K, a.alpha, a.gelu, a.z2, a.transC, a.sCn, a.seq);
}

// ======================================================================
//  orchestration
// ======================================================================
extern "C" void kernel_launch(void* const* d_in, const int* in_sizes, int n_in,
                              void* d_out, int out_size) {
    (void)in_sizes; (void)n_in; (void)out_size;
    const float* x    = (const float*)d_in[0];
    const float* Wp   = (const float*)d_in[1];
    const float* bp   = (const float*)d_in[2];
    const float* cls  = (const float*)d_in[3];
    const float* ln1g = (const float*)d_in[4];
    const float* ln1b = (const float*)d_in[5];
    const float* Wq   = (const float*)d_in[6];
    const float* bq   = (const float*)d_in[7];
    const float* Wk   = (const float*)d_in[8];
    const float* bk   = (const float*)d_in[9];
    const float* Wv   = (const float*)d_in[10];
    const float* bv   = (const float*)d_in[11];
    const float* ln2g = (const float*)d_in[12];
    const float* ln2b = (const float*)d_in[13];
    const float* W1   = (const float*)d_in[14];
    const float* b1   = (const float*)d_in[15];
    const float* W2   = (const float*)d_in[16];
    const float* b2   = (const float*)d_in[17];
    const float* Wh   = (const float*)d_in[18];
    const float* bh   = (const float*)d_in[19];
    float* out_final  = (float*)d_out;

    float *outb, *att, *ptmp;
    __half *ph, *xh, *mh, *qh, *kh, *vth, *ath;
    __half *wph, *w1h, *w2h, *wqh, *wkh, *wvh;
    cudaGetSymbolAddress((void**)&outb, g_out);
    cudaGetSymbolAddress((void**)&att,  g_att);
    cudaGetSymbolAddress((void**)&ptmp, g_ptmp);
    cudaGetSymbolAddress((void**)&ph,   g_ph);
    cudaGetSymbolAddress((void**)&xh,   g_xh);
    cudaGetSymbolAddress((void**)&mh,   g_mh);
    cudaGetSymbolAddress((void**)&qh,   g_qh);
    cudaGetSymbolAddress((void**)&kh,   g_kh);
    cudaGetSymbolAddress((void**)&vth,  g_vth);
    cudaGetSymbolAddress((void**)&ath,  g_ath);
    cudaGetSymbolAddress((void**)&wph,  g_wph);
    cudaGetSymbolAddress((void**)&w1h,  g_w1h);
    cudaGetSymbolAddress((void**)&w2h,  g_w2h);
    cudaGetSymbolAddress((void**)&wqh,  g_wqh);
    cudaGetSymbolAddress((void**)&wkh,  g_wkh);
    cudaGetSymbolAddress((void**)&wvh,  g_wvh);

    cudaStream_t stream = 0;
    const long long SD = (long long)SEQ * DIM;
    const long long SA = (long long)SEQ * ALD;       // per-(n,h) att slab
    const long long VA = (long long)DH * ALD;        // per-(n,h) vT slab
    const int ROWS = BATCH * SEQ;                    // 12608

    // 0) weight converts + vT pad zero (deterministic every run)
    {
        long long n;
        n = (long long)DIM * DIM;
        cvt_kernel<<<(unsigned)((n / 4 + 255) / 256), 256, 0, stream>>>(Wp, wph, n);
        n = (long long)NLAYER * MLPD * DIM;
        cvt_kernel<<<(unsigned)((n / 4 + 255) / 256), 256, 0, stream>>>(W1, w1h, n);
        cvt_kernel<<<(unsigned)((n / 4 + 255) / 256), 256, 0, stream>>>(W2, w2h, n);
        n = (long long)NLAYER * NHEAD * DH * DH;
        cvt_kernel<<<(unsigned)((n / 4 + 255) / 256), 256, 0, stream>>>(Wq, wqh, n);
        cvt_kernel<<<(unsigned)((n / 4 + 255) / 256), 256, 0, stream>>>(Wk, wkh, n);
        cvt_kernel<<<(unsigned)((n / 4 + 255) / 256), 256, 0, stream>>>(Wv, wvh, n);
        n = (long long)BATCH * NHEAD * DH * ALD;
        zero_fp16_kernel<<<(unsigned)((n + 255) / 256), 256, 0, stream>>>(vth, n);
    }

    // 1) patchify -> fp16
    {
        long long total = (long long)BATCH * NPATCH * DIM;
        patchify_kernel<<<(unsigned)((total + 255) / 256), 256, 0, stream>>>(x, ph);
    }
    // 2) patch embedding: ptmp = patches @ Wp^T + bp
    {
        MArgs a = {};
        a.Ah = ph; a.lda = DIM;
        a.Bh = wph; a.ldb = DIM;
        a.Cf = ptmp; a.ldc = DIM;
        a.bias = bp;
        a.M = BATCH * NPATCH; a.N = DIM; a.K = DIM; a.alpha = 1.f;
        a.z2 = 1; a.Z = 1; a.seq = SEQ;
        launch_mma(a, stream);
    }
    // 3) assemble tokens + cls + positional embedding
    {
        long long total = (long long)BATCH * SEQ * DIM;
        assemble_kernel<<<(unsigned)((total + 255) / 256), 256, 0, stream>>>(ptmp, cls, outb);
    }

    for (int l = 0; l < NLAYER; l++) {
        // --- ln1 -> fp16 ---
        layernorm_kernel<<<ROWS, 256, 0, stream>>>(outb, ln1g + l * DIM, ln1b + l * DIM, xh);

        // --- Q, K projections (per-head batch Z=12) ---
        const long long WOFF = (long long)l * NHEAD * DH * DH;
        {
            MArgs a = {};
            a.Ah = xh; a.lda = DIM; a.sA1 = DH;
            a.Bh = wqh + WOFF; a.ldb = DH; a.sB1 = (long long)DH * DH;
            a.Ch = qh; a.ldc = DIM; a.sC1 = DH;
            a.bias = bq + (long long)l * NHEAD * DH; a.sb1 = DH;
            a.M = ROWS; a.N = DH; a.K = DH; a.alpha = 1.f;
            a.z2 = 1; a.Z = NHEAD; a.seq = SEQ;
            launch_mma(a, stream);
            a.Bh = wkh + WOFF;
            a.Ch = kh;
            a.bias = bk + (long long)l * NHEAD * DH;
            launch_mma(a, stream);
        }
        // --- V projection -> transposed vT[n][h][o][s] ---
        {
            MArgs a = {};
            a.Ah = xh; a.lda = DIM; a.sA1 = DH;
            a.Bh = wvh + WOFF; a.ldb = DH; a.sB1 = (long long)DH * DH;
            a.Ch = vth; a.ldc = ALD; a.sC1 = VA;
            a.bias = bv + (long long)l * NHEAD * DH; a.sb1 = DH;
            a.M = ROWS; a.N = DH; a.K = DH; a.alpha = 1.f;
            a.z2 = 1; a.Z = NHEAD; a.seq = SEQ;
            a.transC = 1; a.sCn = (long long)NHEAD * VA;
            launch_mma(a, stream);
        }

        // --- scores: att[z] = q[z] @ k[z]^T / 8   (Z = 768) ---
        {
            MArgs a = {};
            a.Ah = qh; a.lda = DIM; a.sA1 = SD; a.sA2 = DH;
            a.Bh = kh; a.ldb = DIM; a.sB1 = SD; a.sB2 = DH;
            a.Cf = att; a.ldc = ALD; a.sC1 = (long long)NHEAD * SA; a.sC2 = SA;
            a.M = SEQ; a.N = SEQ; a.K = DH; a.alpha = 0.125f;
            a.z2 = NHEAD; a.Z = BATCH * NHEAD; a.seq = SEQ;
            launch_mma(a, stream);
        }
        // --- softmax -> fp16 probs (zero pad to 224) ---
        softmax_kernel<<<BATCH * NHEAD * SEQ, 256, 0, stream>>>(att, ath);

        // --- AV + residual ---
        {
            MArgs a = {};
            a.Ah = ath; a.lda = ALD; a.sA1 = (long long)NHEAD * SA; a.sA2 = SA;
            a.Bh = vth; a.ldb = ALD; a.sB1 = (long long)NHEAD * VA; a.sB2 = VA;
            a.Cf = outb; a.ldc = DIM; a.sC1 = SD; a.sC2 = DH;
            a.R = outb; a.sR1 = SD; a.sR2 = DH;
            a.M = SEQ; a.N = DH; a.K = ALD; a.alpha = 1.f;
            a.z2 = NHEAD; a.Z = BATCH * NHEAD; a.seq = SEQ;
            launch_mma(a, stream);
        }

        // --- ln2 -> fp16 ---
        layernorm_kernel<<<ROWS, 256, 0, stream>>>(outb, ln2g + l * DIM, ln2b + l * DIM, xh);

        // --- MLP1 + GELU -> fp16 ---
        {
            MArgs a = {};
            a.Ah = xh; a.lda = DIM;
            a.Bh = w1h + (long long)l * MLPD * DIM; a.ldb = DIM;
            a.Ch = mh; a.ldc = MLPD;
            a.bias = b1 + (long long)l * MLPD;
            a.M = ROWS; a.N = MLPD; a.K = DIM; a.alpha = 1.f; a.gelu = 1;
            a.z2 = 1; a.Z = 1; a.seq = SEQ;
            launch_mma(a, stream);
        }
        // --- MLP2 + residual -> fp32 ---
        {
            MArgs a = {};
            a.Ah = mh; a.lda = MLPD;
            a.Bh = w2h + (long long)l * DIM * MLPD; a.ldb = MLPD;
            a.Cf = outb; a.ldc = DIM;
            a.bias = b2 + (long long)l * DIM;
            a.R = outb;
            a.M = ROWS; a.N = DIM; a.K = MLPD; a.alpha = 1.f;
            a.z2 = 1; a.Z = 1; a.seq = SEQ;
            launch_mma(a, stream);
        }
    }

    // --- head: out_final = out[:,0,:] @ Wh^T + bh (SIMT, tiny) ---
    {
        dim3 grid((OUTD + BN - 1) / BN, (BATCH + BM - 1) / BM, 1);
        gemm_simt_kernel<<<grid, 256, 0, stream>>>(
            outb, (int)SD, Wh, DIM, out_final, OUTD, bh, BATCH, OUTD, DIM);
    }
}

// round 6
// speedup vs baseline: 9.4251x; 1.3337x over previous
#include <cuda_runtime.h>
#include <cuda_fp16.h>
#include <cstdint>

// ---------------- problem constants ----------------
#define BATCH 64
#define SEQ 197
#define NPATCH 196
#define DIM 768
#define NHEAD 12
#define DH 64
#define MLPD 3072
#define OUTD 1000
#define NLAYER 12
#define ALD 224                 // padded attention K length (mult of 32)

// ---------------- scratch (static device globals; no allocation) ----------------
__device__ float g_out[(long long)BATCH * SEQ * DIM];          // residual stream
__device__ float g_ptmp[(long long)BATCH * NPATCH * DIM];      // patch-embed fp32 out

// fp16 activation / weight buffers
__device__ __half g_ph[(long long)BATCH * NPATCH * DIM];   // patches
__device__ __half g_xh[(long long)BATCH * SEQ * DIM];      // ln out
__device__ __half g_mh[(long long)BATCH * SEQ * MLPD];     // mlp hidden
__device__ __half g_qh[(long long)BATCH * SEQ * DIM];
__device__ __half g_kh[(long long)BATCH * SEQ * DIM];
__device__ __half g_vth[(long long)BATCH * NHEAD * DH * ALD];  // V^T [n][h][o][s-pad]
__device__ __half g_wph[(long long)DIM * DIM];
__device__ __half g_w1h[(long long)NLAYER * MLPD * DIM];
__device__ __half g_w2h[(long long)NLAYER * DIM * MLPD];
__device__ __half g_wqh[(long long)NLAYER * NHEAD * DH * DH];
__device__ __half g_wkh[(long long)NLAYER * NHEAD * DH * DH];
__device__ __half g_wvh[(long long)NLAYER * NHEAD * DH * DH];

// ---------------- helpers ----------------
__device__ __forceinline__ uint32_t smem_u32(const void* p) {
    uint32_t a;
    asm("{ .reg .u64 t; cvta.to.shared.u64 t, %1; cvt.u32.u64 %0, t; }" : "=r"(a) : "l"(p));
    return a;
}

__device__ __forceinline__ void ldm4(uint32_t* r, uint32_t addr) {
    asm volatile("ldmatrix.sync.aligned.m8n8.x4.shared.b16 {%0,%1,%2,%3}, [%4];"
                 : "=r"(r[0]), "=r"(r[1]), "=r"(r[2]), "=r"(r[3]) : "r"(addr));
}

__device__ __forceinline__ void mma_fp16(float* c, const uint32_t* a, uint32_t b0, uint32_t b1) {
    asm volatile(
        "mma.sync.aligned.m16n8k16.row.col.f32.f16.f16.f32 "
        "{%0,%1,%2,%3}, {%4,%5,%6,%7}, {%8,%9}, {%0,%1,%2,%3};"
        : "+f"(c[0]), "+f"(c[1]), "+f"(c[2]), "+f"(c[3])
        : "r"(a[0]), "r"(a[1]), "r"(a[2]), "r"(a[3]), "r"(b0), "r"(b1));
}

__device__ __forceinline__ uint32_t pack_h2(float lo, float hi) {
    __half2 h = __floats2half2_rn(lo, hi);
    return *(uint32_t*)&h;
}

__device__ __forceinline__ void cp_async16(uint32_t dst, const void* src, int valid) {
    asm volatile("cp.async.cg.shared.global [%0], [%1], 16, %2;"
                 :: "r"(dst), "l"(src), "r"(valid));
}
__device__ __forceinline__ void cp_commit() { asm volatile("cp.async.commit_group;"); }
__device__ __forceinline__ void cp_wait1() { asm volatile("cp.async.wait_group 1;"); }
__device__ __forceinline__ void cp_wait0() { asm volatile("cp.async.wait_group 0;"); }

// ======================================================================
//  fp16 batched NT GEMM (qkv / mlp / patch-embed)
// ======================================================================
#define RSB 80
#define PLB (128 * RSB)
#define STB (2 * PLB)
#define NSTAGE 3
#define SMEM_MMA (NSTAGE * STB)

__global__ __launch_bounds__(256, 2)
void gemm_fp16_kernel(const __half* __restrict__ Ah, long long lda, long long sA1, long long sA2,
                      const __half* __restrict__ Bh, long long ldb, long long sB1, long long sB2,
                      float* __restrict__ Cf, __half* __restrict__ Ch,
                      long long ldc, long long sC1, long long sC2,
                      const float* __restrict__ bias, long long sb1, long long sb2,
                      const float* __restrict__ R, long long sR1, long long sR2,
                      int M, int N, int K, float alpha, int gelu, int z2,
                      int transC, long long sCn, int seq)
{
    extern __shared__ char sm[];
    uint32_t smb = smem_u32(sm);
    const int tid = threadIdx.x;
    const int lid = tid & 31;
    const int wid = tid >> 5;
    const int wm = wid >> 2;
    const int wn = wid & 3;
    const int m0 = blockIdx.y * 128;
    const int n0 = blockIdx.x * 128;

    {
        int bz = blockIdx.z;
        int i1 = bz / z2, i2 = bz % z2;
        Ah += i1 * sA1 + i2 * sA2;
        Bh += i1 * sB1 + i2 * sB2;
        if (Cf) Cf += i1 * sC1 + i2 * sC2;
        if (Ch) Ch += i1 * sC1 + i2 * sC2;
        if (bias) bias += i1 * sb1 + i2 * sb2;
        if (R) R += i1 * sR1 + i2 * sR2;
    }

    const int nch = K >> 5;

    auto load_stage = [&](int s, int chunk) {
        int k0 = chunk << 5;
        uint32_t sbase = smb + s * STB;
        #pragma unroll
        for (int t = 0; t < 4; t++) {
            int id = tid + t * 256;
            int plane = id >> 9;
            int rc = id & 511;
            int row = rc >> 2;
            int c = rc & 3;
            uint32_t dst = sbase + plane * PLB + row * RSB + c * 16;
            const __half* src;
            int valid;
            if (plane == 0) {
                int gm = m0 + row;
                int gmc = gm < M ? gm : M - 1;
                src = Ah + (long long)gmc * lda + k0 + c * 8;
                valid = (gm < M) ? 16 : 0;
            } else {
                int gn = n0 + row;
                int gnc = gn < N ? gn : N - 1;
                src = Bh + (long long)gnc * ldb + k0 + c * 8;
                valid = (gn < N) ? 16 : 0;
            }
            cp_async16(dst, src, valid);
        }
        cp_commit();
    };

    float acc[4][4][4];
    #pragma unroll
    for (int i = 0; i < 4; i++)
        #pragma unroll
        for (int j = 0; j < 4; j++)
            #pragma unroll
            for (int r = 0; r < 4; r++) acc[i][j][r] = 0.f;

    load_stage(0, 0);
    if (nch > 1) load_stage(1, 1);

    for (int i = 0; i < nch; i++) {
        if (i == nch - 1) cp_wait0(); else cp_wait1();
        __syncthreads();
        if (i + 2 < nch) load_stage((i + 2) % NSTAGE, i + 2);

        uint32_t sA = smb + (i % NSTAGE) * STB;
        uint32_t sB = sA + PLB;
        #pragma unroll
        for (int kk = 0; kk < 2; kk++) {
            int kt = kk << 4;
            uint32_t af[4][4];
            #pragma unroll
            for (int t = 0; t < 4; t++) {
                int m = wm * 64 + t * 16;
                uint32_t row = m + ((lid >> 3) & 1) * 8 + (lid & 7);
                uint32_t koff = kt + (lid >> 4) * 8;
                ldm4(af[t], sA + row * RSB + koff * 2);
            }
            uint32_t bf[2][4];
            #pragma unroll
            for (int p = 0; p < 2; p++) {
                int n = wn * 32 + p * 16;
                uint32_t row = n + (lid >> 4) * 8 + (lid & 7);
                uint32_t koff = kt + ((lid >> 3) & 1) * 8;
                ldm4(bf[p], sB + row * RSB + koff * 2);
            }
            #pragma unroll
            for (int t = 0; t < 4; t++) {
                #pragma unroll
                for (int j = 0; j < 4; j++) {
                    uint32_t b0 = bf[j >> 1][(j & 1) * 2], b1 = bf[j >> 1][(j & 1) * 2 + 1];
                    mma_fp16(acc[t][j], af[t], b0, b1);
                }
            }
        }
        __syncthreads();
    }

    #pragma unroll
    for (int t = 0; t < 4; t++) {
        #pragma unroll
        for (int j = 0; j < 4; j++) {
            int col = n0 + wn * 32 + j * 8 + (lid & 3) * 2;
            #pragma unroll
            for (int h = 0; h < 2; h++) {
                int row = m0 + wm * 64 + t * 16 + (lid >> 2) + h * 8;
                if (row >= M) continue;
                #pragma unroll
                for (int e = 0; e < 2; e++) {
                    int c = col + e;
                    if (c >= N) continue;
                    float v = acc[t][j][h * 2 + e] * alpha;
                    if (bias) v += bias[c];
                    if (gelu) v = 0.5f * v * (1.0f + erff(v * 0.70710678118654752f));
                    if (Cf) {
                        long long base = (long long)row * ldc + c;
                        float r = R ? R[base] : 0.f;
                        Cf[base] = v + r;
                    } else if (!transC) {
                        Ch[(long long)row * ldc + c] = __float2half_rn(v);
                    } else {
                        int nb = row / seq, s = row % seq;
                        Ch[(long long)nb * sCn + (long long)c * ldc + s] = __float2half_rn(v);
                    }
                }
            }
        }
    }
}

// ======================================================================
//  fused flash attention: per (qtile, h, n) CTA
//  scores (mma) -> mask -> softmax (unnormalized) -> AV (mma, P-frag reuse)
//  -> out += residual (in-place on g_out)
// ======================================================================
#define FA_RSQ 144                            // q/k smem row stride bytes (64 fp16 + pad)
#define FA_RSV 464                            // vT smem row stride bytes (224 fp16 + pad)
#define FA_SM_Q 0
#define FA_SM_K (128 * FA_RSQ)                // 18432
#define FA_SM_V (FA_SM_K + ALD * FA_RSQ)      // 18432 + 32256 = 50688
#define FA_SMEM (FA_SM_V + DH * FA_RSV)       // + 29696 = 80384

__global__ __launch_bounds__(256, 1)
void flash_kernel(const __half* __restrict__ qh, const __half* __restrict__ kh,
                  const __half* __restrict__ vth, float* __restrict__ outb)
{
    extern __shared__ char sm[];
    uint32_t smb = smem_u32(sm);
    const int tid = threadIdx.x;
    const int lid = tid & 31;
    const int wid = tid >> 5;
    const int q0 = blockIdx.x * 128;
    const int h  = blockIdx.y;
    const int n  = blockIdx.z;
    const int wr = wid * 16;                  // warp's 16-row strip within q tile

    const long long qbase = ((long long)n * SEQ) * DIM + h * DH;
    const long long vbase = ((long long)n * NHEAD + h) * (long long)DH * ALD;

    // ---- load q (128x64), k (224x64, clamp), vT (64x224) into smem ----
    #pragma unroll
    for (int t = 0; t < 4; t++) {
        int id = tid + t * 256;               // 1024: q chunks
        int row = id >> 3, ch = id & 7;
        int s = q0 + row; if (s >= SEQ) s = SEQ - 1;
        *(uint4*)(sm + FA_SM_Q + row * FA_RSQ + ch * 16) =
            *(const uint4*)(qh + qbase + (long long)s * DIM + ch * 8);
    }
    #pragma unroll
    for (int t = 0; t < 7; t++) {
        int id = tid + t * 256;               // 1792: k chunks
        int row = id >> 3, ch = id & 7;
        int s = row; if (s >= SEQ) s = SEQ - 1;
        *(uint4*)(sm + FA_SM_K + row * FA_RSQ + ch * 16) =
            *(const uint4*)(kh + qbase + (long long)s * DIM + ch * 8);
    }
    for (int id = tid; id < DH * 28; id += 256) {   // 1792: vT chunks
        int row = id / 28, ch = id % 28;
        *(uint4*)(sm + FA_SM_V + row * FA_RSV + ch * 16) =
            *(const uint4*)(vth + vbase + (long long)row * ALD + ch * 8);
    }
    __syncthreads();

    // ---- scores: 16 rows x 224 cols per warp, fp32 accum ----
    uint32_t aq[4][4];
    #pragma unroll
    for (int kt = 0; kt < 4; kt++) {
        uint32_t row = wr + ((lid >> 3) & 1) * 8 + (lid & 7);
        uint32_t koff = kt * 16 + (lid >> 4) * 8;
        ldm4(aq[kt], smb + FA_SM_Q + row * FA_RSQ + koff * 2);
    }
    float acc[28][4];
    #pragma unroll
    for (int j = 0; j < 28; j++)
        #pragma unroll
        for (int r = 0; r < 4; r++) acc[j][r] = 0.f;

    #pragma unroll
    for (int nt = 0; nt < 14; nt++) {
        #pragma unroll
        for (int kt = 0; kt < 4; kt++) {
            uint32_t bk[4];
            uint32_t row = nt * 16 + (lid >> 4) * 8 + (lid & 7);
            uint32_t koff = kt * 16 + ((lid >> 3) & 1) * 8;
            ldm4(bk, smb + FA_SM_K + row * FA_RSQ + koff * 2);
            mma_fp16(acc[nt * 2],     aq[kt], bk[0], bk[1]);
            mma_fp16(acc[nt * 2 + 1], aq[kt], bk[2], bk[3]);
        }
    }

    // ---- mask cols >= SEQ, softmax over k (scale 1/8 folded into exp) ----
    float m0 = -1e30f, m1 = -1e30f;
    #pragma unroll
    for (int j = 0; j < 28; j++) {
        int c0 = j * 8 + (lid & 3) * 2;
        if (c0 >= SEQ)     { acc[j][0] = -1e30f; acc[j][2] = -1e30f; }
        if (c0 + 1 >= SEQ) { acc[j][1] = -1e30f; acc[j][3] = -1e30f; }
        m0 = fmaxf(m0, fmaxf(acc[j][0], acc[j][1]));
        m1 = fmaxf(m1, fmaxf(acc[j][2], acc[j][3]));
    }
    m0 = fmaxf(m0, __shfl_xor_sync(0xffffffffu, m0, 1));
    m0 = fmaxf(m0, __shfl_xor_sync(0xffffffffu, m0, 2));
    m1 = fmaxf(m1, __shfl_xor_sync(0xffffffffu, m1, 1));
    m1 = fmaxf(m1, __shfl_xor_sync(0xffffffffu, m1, 2));

    float s0 = 0.f, s1 = 0.f;
    #pragma unroll
    for (int j = 0; j < 28; j++) {
        acc[j][0] = expf((acc[j][0] - m0) * 0.125f);
        acc[j][1] = expf((acc[j][1] - m0) * 0.125f);
        acc[j][2] = expf((acc[j][2] - m1) * 0.125f);
        acc[j][3] = expf((acc[j][3] - m1) * 0.125f);
        s0 += acc[j][0] + acc[j][1];
        s1 += acc[j][2] + acc[j][3];
    }
    s0 += __shfl_xor_sync(0xffffffffu, s0, 1);
    s0 += __shfl_xor_sync(0xffffffffu, s0, 2);
    s1 += __shfl_xor_sync(0xffffffffu, s1, 1);
    s1 += __shfl_xor_sync(0xffffffffu, s1, 2);
    float inv0 = 1.0f / s0, inv1 = 1.0f / s1;

    // ---- AV: P (C-frag -> A-frag reuse) @ vT ----
    float o[8][4];
    #pragma unroll
    for (int g = 0; g < 8; g++)
        #pragma unroll
        for (int r = 0; r < 4; r++) o[g][r] = 0.f;

    #pragma unroll
    for (int kt2 = 0; kt2 < 14; kt2++) {
        int j0 = kt2 * 2, j1 = j0 + 1;
        uint32_t af[4];
        af[0] = pack_h2(acc[j0][0], acc[j0][1]);
        af[1] = pack_h2(acc[j0][2], acc[j0][3]);
        af[2] = pack_h2(acc[j1][0], acc[j1][1]);
        af[3] = pack_h2(acc[j1][2], acc[j1][3]);
        #pragma unroll
        for (int g = 0; g < 4; g++) {
            uint32_t bv[4];
            uint32_t row = g * 16 + (lid >> 4) * 8 + (lid & 7);
            uint32_t koff = kt2 * 16 + ((lid >> 3) & 1) * 8;
            ldm4(bv, smb + FA_SM_V + row * FA_RSV + koff * 2);
            mma_fp16(o[g * 2],     af, bv[0], bv[1]);
            mma_fp16(o[g * 2 + 1], af, bv[2], bv[3]);
        }
    }

    // ---- epilogue: normalize + residual add (in place) ----
    int r0 = q0 + wr + (lid >> 2);
    int r1 = r0 + 8;
    #pragma unroll
    for (int g = 0; g < 8; g++) {
        int c = h * DH + g * 8 + (lid & 3) * 2;
        if (r0 < SEQ) {
            long long b = ((long long)n * SEQ + r0) * DIM + c;
            outb[b]     += o[g][0] * inv0;
            outb[b + 1] += o[g][1] * inv0;
        }
        if (r1 < SEQ) {
            long long b = ((long long)n * SEQ + r1) * DIM + c;
            outb[b]     += o[g][2] * inv1;
            outb[b + 1] += o[g][3] * inv1;
        }
    }
}

// ======================================================================
//  small kernels
// ======================================================================
__global__ void zero_fp16_kernel(__half* __restrict__ p, long long n) {
    long long i = (long long)blockIdx.x * 256 + threadIdx.x;
    if (i < n) p[i] = __float2half(0.f);
}

__global__ void cvt_kernel(const float* __restrict__ x, __half* __restrict__ h, long long n) {
    long long i = ((long long)blockIdx.x * 256 + threadIdx.x) * 4;
    if (i >= n) return;
    float4 v = *(const float4*)(x + i);
    h[i]     = __float2half_rn(v.x);
    h[i + 1] = __float2half_rn(v.y);
    h[i + 2] = __float2half_rn(v.z);
    h[i + 3] = __float2half_rn(v.w);
}

__global__ void patchify_kernel(const float* __restrict__ x, __half* __restrict__ ph) {
    long long idx = (long long)blockIdx.x * 256 + threadIdx.x;
    const long long total = (long long)BATCH * NPATCH * DIM;
    if (idx >= total) return;
    int e = (int)(idx % DIM);
    long long r = idx / DIM;
    int p = (int)(r % NPATCH);
    int n = (int)(r / NPATCH);
    int c = e / 256;
    int hw = e % 256;
    int hi = hw / 16, wi = hw % 16;
    int pi = p / 14, pj = p % 14;
    ph[idx] = __float2half_rn(
        x[(((long long)n * 3 + c) * 224 + (pi * 16 + hi)) * 224 + (pj * 16 + wi)]);
}

__global__ void assemble_kernel(const float* __restrict__ tmp, const float* __restrict__ cls,
                                float* __restrict__ out) {
    long long idx = (long long)blockIdx.x * 256 + threadIdx.x;
    const long long total = (long long)BATCH * SEQ * DIM;
    if (idx >= total) return;
    int d = (int)(idx % DIM);
    long long r = idx / DIM;
    int s = (int)(r % SEQ);
    int n = (int)(r / SEQ);
    float v = (s == 0) ? cls[d] : tmp[((long long)n * NPATCH + (s - 1)) * DIM + d];
    float pe;
    if ((s & 1) == 0) pe = sinf((float)s / powf(10000.0f, (float)d / (float)DIM));
    else              pe = cosf((float)s / powf(10000.0f, (float)(d - 1) / (float)DIM));
    out[idx] = v + pe;
}

__global__ void layernorm_kernel(const float* __restrict__ x, const float* __restrict__ g,
                                 const float* __restrict__ b, __half* __restrict__ yh) {
    long long row = blockIdx.x;
    const float* p = x + row * DIM;
    __shared__ float s1[256], s2[256];
    int t = threadIdx.x;
    float a = 0.f, a2 = 0.f;
    for (int j = t; j < DIM; j += 256) { float v = p[j]; a += v; a2 += v * v; }
    s1[t] = a; s2[t] = a2; __syncthreads();
    for (int s = 128; s > 0; s >>= 1) {
        if (t < s) { s1[t] += s1[t + s]; s2[t] += s2[t + s]; }
        __syncthreads();
    }
    float mu = s1[0] * (1.0f / DIM);
    float var = s2[0] * (1.0f / DIM) - mu * mu;
    float inv = rsqrtf(var + 1e-5f);
    for (int j = t; j < DIM; j += 256)
        yh[row * DIM + j] = __float2half_rn((p[j] - mu) * inv * g[j] + b[j]);
}

// ======================================================================
//  generic SIMT GEMM (head only)
// ======================================================================
#define BM 64
#define BN 64
#define BK 16

__global__ void gemm_simt_kernel(
    const float* __restrict__ A, int lda,
    const float* __restrict__ B, int ldb,
    float* __restrict__ C, int ldc,
    const float* __restrict__ bias,
    int M, int N, int K)
{
    __shared__ float As[BK][BM];
    __shared__ float Bs[BK][BN];
    int bm = blockIdx.y * BM;
    int bn = blockIdx.x * BN;
    int tid = threadIdx.x;
    int tx = tid % 16, ty = tid / 16;
    float acc[4][4] = {};
    for (int k0 = 0; k0 < K; k0 += BK) {
        #pragma unroll
        for (int i = 0; i < 4; i++) {
            int idx = tid + i * 256;
            int m = idx / BK, kk = idx % BK;
            int gm = bm + m, gk = k0 + kk;
            As[kk][m] = (gm < M && gk < K) ? A[(long long)gm * lda + gk] : 0.f;
        }
        #pragma unroll
        for (int i = 0; i < 4; i++) {
            int idx = tid + i * 256;
            int n = idx / BK, kk = idx % BK;
            int gn = bn + n, gk = k0 + kk;
            Bs[kk][n] = (gn < N && gk < K) ? B[(long long)gn * ldb + gk] : 0.f;
        }
        __syncthreads();
        #pragma unroll
        for (int kk = 0; kk < BK; kk++) {
            float a[4], b[4];
            #pragma unroll
            for (int i = 0; i < 4; i++) a[i] = As[kk][ty * 4 + i];
            #pragma unroll
            for (int j = 0; j < 4; j++) b[j] = Bs[kk][tx * 4 + j];
            #pragma unroll
            for (int i = 0; i < 4; i++)
                #pragma unroll
                for (int j = 0; j < 4; j++)
                    acc[i][j] += a[i] * b[j];
        }
        __syncthreads();
    }
    #pragma unroll
    for (int i = 0; i < 4; i++) {
        int gm = bm + ty * 4 + i;
        if (gm >= M) continue;
        #pragma unroll
        for (int j = 0; j < 4; j++) {
            int gn = bn + tx * 4 + j;
            if (gn >= N) continue;
            C[(long long)gm * ldc + gn] = acc[i][j] + (bias ? bias[gn] : 0.f);
        }
    }
}

// ======================================================================
//  launch helper
// ======================================================================
struct MArgs {
    const __half *Ah; long long lda, sA1, sA2;
    const __half *Bh; long long ldb, sB1, sB2;
    float* Cf; __half* Ch; long long ldc, sC1, sC2;
    const float* bias; long long sb1, sb2;
    const float* R; long long sR1, sR2;
    int M, N, K; float alpha; int gelu; int z2; int Z;
    int transC; long long sCn; int seq;
};

static void launch_mma(const MArgs& a, cudaStream_t stream) {
    static bool attr_set = false;
    if (!attr_set) {
        cudaFuncSetAttribute(gemm_fp16_kernel,
                             cudaFuncAttributeMaxDynamicSharedMemorySize, SMEM_MMA);
        cudaFuncSetAttribute(flash_kernel,
                             cudaFuncAttributeMaxDynamicSharedMemorySize, FA_SMEM);
        attr_set = true;
    }
    dim3 grid((a.N + 127) / 128, (a.M + 127) / 128, a.Z);
    gemm_fp16_kernel<<<grid, 256, SMEM_MMA, stream>>>(
        a.Ah, a.lda, a.sA1, a.sA2,
        a.Bh, a.ldb, a.sB1, a.sB2,
        a.Cf, a.Ch, a.ldc, a.sC1, a.sC2,
        a.bias, a.sb1, a.sb2, a.R, a.sR1, a.sR2,
        a.M, a.N, a.K, a.alpha, a.gelu, a.z2, a.transC, a.sCn, a.seq);
}

// ======================================================================
//  orchestration
// ======================================================================
extern "C" void kernel_launch(void* const* d_in, const int* in_sizes, int n_in,
                              void* d_out, int out_size) {
    (void)in_sizes; (void)n_in; (void)out_size;
    const float* x    = (const float*)d_in[0];
    const float* Wp   = (const float*)d_in[1];
    const float* bp   = (const float*)d_in[2];
    const float* cls  = (const float*)d_in[3];
    const float* ln1g = (const float*)d_in[4];
    const float* ln1b = (const float*)d_in[5];
    const float* Wq   = (const float*)d_in[6];
    const float* bq   = (const float*)d_in[7];
    const float* Wk   = (const float*)d_in[8];
    const float* bk   = (const float*)d_in[9];
    const float* Wv   = (const float*)d_in[10];
    const float* bv   = (const float*)d_in[11];
    const float* ln2g = (const float*)d_in[12];
    const float* ln2b = (const float*)d_in[13];
    const float* W1   = (const float*)d_in[14];
    const float* b1   = (const float*)d_in[15];
    const float* W2   = (const float*)d_in[16];
    const float* b2   = (const float*)d_in[17];
    const float* Wh   = (const float*)d_in[18];
    const float* bh   = (const float*)d_in[19];
    float* out_final  = (float*)d_out;

    float *outb, *ptmp;
    __half *ph, *xh, *mh, *qh, *kh, *vth;
    __half *wph, *w1h, *w2h, *wqh, *wkh, *wvh;
    cudaGetSymbolAddress((void**)&outb, g_out);
    cudaGetSymbolAddress((void**)&ptmp, g_ptmp);
    cudaGetSymbolAddress((void**)&ph,   g_ph);
    cudaGetSymbolAddress((void**)&xh,   g_xh);
    cudaGetSymbolAddress((void**)&mh,   g_mh);
    cudaGetSymbolAddress((void**)&qh,   g_qh);
    cudaGetSymbolAddress((void**)&kh,   g_kh);
    cudaGetSymbolAddress((void**)&vth,  g_vth);
    cudaGetSymbolAddress((void**)&wph,  g_wph);
    cudaGetSymbolAddress((void**)&w1h,  g_w1h);
    cudaGetSymbolAddress((void**)&w2h,  g_w2h);
    cudaGetSymbolAddress((void**)&wqh,  g_wqh);
    cudaGetSymbolAddress((void**)&wkh,  g_wkh);
    cudaGetSymbolAddress((void**)&wvh,  g_wvh);

    cudaStream_t stream = 0;
    const long long VA = (long long)DH * ALD;        // per-(n,h) vT slab
    const int ROWS = BATCH * SEQ;                    // 12608

    // 0) weight converts + vT pad zero
    {
        long long n;
        n = (long long)DIM * DIM;
        cvt_kernel<<<(unsigned)((n / 4 + 255) / 256), 256, 0, stream>>>(Wp, wph, n);
        n = (long long)NLAYER * MLPD * DIM;
        cvt_kernel<<<(unsigned)((n / 4 + 255) / 256), 256, 0, stream>>>(W1, w1h, n);
        cvt_kernel<<<(unsigned)((n / 4 + 255) / 256), 256, 0, stream>>>(W2, w2h, n);
        n = (long long)NLAYER * NHEAD * DH * DH;
        cvt_kernel<<<(unsigned)((n / 4 + 255) / 256), 256, 0, stream>>>(Wq, wqh, n);
        cvt_kernel<<<(unsigned)((n / 4 + 255) / 256), 256, 0, stream>>>(Wk, wkh, n);
        cvt_kernel<<<(unsigned)((n / 4 + 255) / 256), 256, 0, stream>>>(Wv, wvh, n);
        n = (long long)BATCH * NHEAD * DH * ALD;
        zero_fp16_kernel<<<(unsigned)((n + 255) / 256), 256, 0, stream>>>(vth, n);
    }

    // 1) patchify -> fp16
    {
        long long total = (long long)BATCH * NPATCH * DIM;
        patchify_kernel<<<(unsigned)((total + 255) / 256), 256, 0, stream>>>(x, ph);
    }
    // 2) patch embedding: ptmp = patches @ Wp^T + bp
    {
        MArgs a = {};
        a.Ah = ph; a.lda = DIM;
        a.Bh = wph; a.ldb = DIM;
        a.Cf = ptmp; a.ldc = DIM;
        a.bias = bp;
        a.M = BATCH * NPATCH; a.N = DIM; a.K = DIM; a.alpha = 1.f;
        a.z2 = 1; a.Z = 1; a.seq = SEQ;
        launch_mma(a, stream);
    }
    // 3) assemble tokens + cls + positional embedding
    {
        long long total = (long long)BATCH * SEQ * DIM;
        assemble_kernel<<<(unsigned)((total + 255) / 256), 256, 0, stream>>>(ptmp, cls, outb);
    }

    for (int l = 0; l < NLAYER; l++) {
        // --- ln1 -> fp16 ---
        layernorm_kernel<<<ROWS, 256, 0, stream>>>(outb, ln1g + l * DIM, ln1b + l * DIM, xh);

        // --- Q, K projections (per-head batch Z=12) ---
        const long long WOFF = (long long)l * NHEAD * DH * DH;
        {
            MArgs a = {};
            a.Ah = xh; a.lda = DIM; a.sA1 = DH;
            a.Bh = wqh + WOFF; a.ldb = DH; a.sB1 = (long long)DH * DH;
            a.Ch = qh; a.ldc = DIM; a.sC1 = DH;
            a.bias = bq + (long long)l * NHEAD * DH; a.sb1 = DH;
            a.M = ROWS; a.N = DH; a.K = DH; a.alpha = 1.f;
            a.z2 = 1; a.Z = NHEAD; a.seq = SEQ;
            launch_mma(a, stream);
            a.Bh = wkh + WOFF;
            a.Ch = kh;
            a.bias = bk + (long long)l * NHEAD * DH;
            launch_mma(a, stream);
        }
        // --- V projection -> transposed vT[n][h][o][s] ---
        {
            MArgs a = {};
            a.Ah = xh; a.lda = DIM; a.sA1 = DH;
            a.Bh = wvh + WOFF; a.ldb = DH; a.sB1 = (long long)DH * DH;
            a.Ch = vth; a.ldc = ALD; a.sC1 = VA;
            a.bias = bv + (long long)l * NHEAD * DH; a.sb1 = DH;
            a.M = ROWS; a.N = DH; a.K = DH; a.alpha = 1.f;
            a.z2 = 1; a.Z = NHEAD; a.seq = SEQ;
            a.transC = 1; a.sCn = (long long)NHEAD * VA;
            launch_mma(a, stream);
        }

        // --- fused attention + residual ---
        {
            dim3 grid(2, NHEAD, BATCH);
            flash_kernel<<<grid, 256, FA_SMEM, stream>>>(qh, kh, vth, outb);
        }

        // --- ln2 -> fp16 ---
        layernorm_kernel<<<ROWS, 256, 0, stream>>>(outb, ln2g + l * DIM, ln2b + l * DIM, xh);

        // --- MLP1 + GELU -> fp16 ---
        {
            MArgs a = {};
            a.Ah = xh; a.lda = DIM;
            a.Bh = w1h + (long long)l * MLPD * DIM; a.ldb = DIM;
            a.Ch = mh; a.ldc = MLPD;
            a.bias = b1 + (long long)l * MLPD;
            a.M = ROWS; a.N = MLPD; a.K = DIM; a.alpha = 1.f; a.gelu = 1;
            a.z2 = 1; a.Z = 1; a.seq = SEQ;
            launch_mma(a, stream);
        }
        // --- MLP2 + residual -> fp32 ---
        {
            MArgs a = {};
            a.Ah = mh; a.lda = MLPD;
            a.Bh = w2h + (long long)l * DIM * MLPD; a.ldb = MLPD;
            a.Cf = outb; a.ldc = DIM;
            a.bias = b2 + (long long)l * DIM;
            a.R = outb;
            a.M = ROWS; a.N = DIM; a.K = MLPD; a.alpha = 1.f;
            a.z2 = 1; a.Z = 1; a.seq = SEQ;
            launch_mma(a, stream);
        }
    }

    // --- head: out_final = out[:,0,:] @ Wh^T + bh (SIMT, tiny) ---
    {
        dim3 grid((OUTD + BN - 1) / BN, (BATCH + BM - 1) / BM, 1);
        gemm_simt_kernel<<<grid, 256, 0, stream>>>(
            outb, (int)((long long)SEQ * DIM), Wh, DIM, out_final, OUTD, bh, BATCH, OUTD, DIM);
    }
}